// round 11
// baseline (speedup 1.0000x reference)
#include <cuda_runtime.h>
#include <math.h>

// ---------------- problem constants ----------------
#define NB   8
#define NC   256
#define NG   4
#define CG   64
#define NHH  4
#define WW   128
#define HWSZ 16384        // 128*128
#define LP   1024         // pooled spatial (32*32)
#define DH   256          // LP/NH
#define DV   4096         // HW/NH

// ---------------- scratch ----------------
__device__ float g_xp [NB*NC*LP];
__device__ float g_q  [NB*NC*LP];
__device__ float g_k  [NB*NC*LP];
__device__ float g_v  [NB*NC*HWSZ];          // holds vd (dw output, tf32-rounded)
__device__ float g_sim[NB*NHH*256*256];
__device__ float g_msim[NB*NHH*256*256];
__device__ float g_bias[NHH*256*256];
__device__ float g_invq[NB*NHH*256];
__device__ float g_invk[NB*NHH*256];
__device__ float g_mbias[NB*NHH*256];

// ---------------- helpers ----------------
__device__ __forceinline__ float warpRedSum(float v){
#pragma unroll
    for (int o = 16; o > 0; o >>= 1) v += __shfl_xor_sync(0xffffffffu, v, o);
    return v;
}
__device__ __forceinline__ float warpRedMax(float v){
#pragma unroll
    for (int o = 16; o > 0; o >>= 1) v = fmaxf(v, __shfl_xor_sync(0xffffffffu, v, o));
    return v;
}
__device__ __forceinline__ float warpRedMin(float v){
#pragma unroll
    for (int o = 16; o > 0; o >>= 1) v = fminf(v, __shfl_xor_sync(0xffffffffu, v, o));
    return v;
}
__device__ __forceinline__ unsigned f2tf(float f){
    unsigned u; asm("cvt.rna.tf32.f32 %0, %1;" : "=r"(u) : "f"(f)); return u;
}
__device__ __forceinline__ void mma8(float* c, unsigned a0, unsigned a1, unsigned a2, unsigned a3,
                                     unsigned b0, unsigned b1){
    asm volatile("mma.sync.aligned.m16n8k8.row.col.f32.tf32.tf32.f32 "
                 "{%0,%1,%2,%3},{%4,%5,%6,%7},{%8,%9},{%0,%1,%2,%3};"
                 : "+f"(c[0]), "+f"(c[1]), "+f"(c[2]), "+f"(c[3])
                 : "r"(a0), "r"(a1), "r"(a2), "r"(a3), "r"(b0), "r"(b1));
}
#define CP_ASYNC16(saddr, gptr) \
    asm volatile("cp.async.cg.shared.global [%0], [%1], 16;" :: "r"(saddr), "l"(gptr))
#define CP_COMMIT  asm volatile("cp.async.commit_group;")
#define CP_WAIT0   asm volatile("cp.async.wait_group 0;")

// ---------------- K1: 4x4 maxpool ----------------
__global__ void k_maxpool(const float* __restrict__ xin, float* __restrict__ out){
    int idx = blockIdx.x * 256 + threadIdx.x;
    int pp = idx & 1023;
    int bc = idx >> 10;
    int ph = pp >> 5, pw = pp & 31;
    const float* xp = xin + (long)bc * HWSZ + (ph * 4) * WW + pw * 4;
    float m = -3.4e38f;
#pragma unroll
    for (int i = 0; i < 4; i++)
#pragma unroll
        for (int j = 0; j < 4; j++)
            m = fmaxf(m, xp[i * WW + j]);
    out[idx] = m;
}

// ---------------- K2: grouped 1x1 pw conv (pooled q/k path, small) ----------------
__global__ void k_grouped_pw(const float* __restrict__ in, const float* __restrict__ w,
                             const float* __restrict__ bias, float* __restrict__ out, int L){
    __shared__ float wsT[64 * 64];
    __shared__ float xs[64][128];
    int g = blockIdx.y, b = blockIdx.z;
    int l0 = blockIdx.x * 128;
    int t = threadIdx.x;
    for (int idx = t; idx < 4096; idx += 128){
        int i = idx >> 6, j = idx & 63;
        wsT[j * 64 + i] = w[g * 4096 + idx];
    }
    const float* ip = in + ((long)(b * NC + g * CG)) * L + l0;
#pragma unroll 8
    for (int j = 0; j < 64; j++) xs[j][t] = ip[(long)j * L + t];
    __syncthreads();
    float acc[64];
#pragma unroll
    for (int i = 0; i < 64; i++) acc[i] = 0.f;
#pragma unroll 4
    for (int j = 0; j < 64; j++){
        float xv = xs[j][t];
        const float4* wr = (const float4*)(wsT + j * 64);
#pragma unroll
        for (int i4 = 0; i4 < 16; i4++){
            float4 wv = wr[i4];
            acc[i4*4+0] += wv.x * xv;
            acc[i4*4+1] += wv.y * xv;
            acc[i4*4+2] += wv.z * xv;
            acc[i4*4+3] += wv.w * xv;
        }
    }
    float* op = out + ((long)(b * NC + g * CG)) * L + l0;
#pragma unroll 8
    for (int i = 0; i < 64; i++)
        op[(long)i * L + t] = acc[i] + bias[g * CG + i];
}

// ---------------- K3: depthwise 3x3 + relu, one channel plane per CTA ----------------
// grid (NC, NB), 256 threads. smem plane 128x129 (pad -> conflict-free column reads).
// Output rounded to tf32 so k_fused's cp.async truncation is lossless.
__global__ void __launch_bounds__(256)
k_dw(const float* __restrict__ x, const float* __restrict__ dw_w,
     const float* __restrict__ dw_b, float* __restrict__ vd){
    extern __shared__ float xs[];          // 128*129 floats = 66048 B
    int c = blockIdx.x, b = blockIdx.y;
    const float* xp = x + ((long)(b * NC + c)) * HWSZ;
    int t = threadIdx.x;

#pragma unroll
    for (int i = 0; i < 16; i++){
        int vid = t + i * 256;             // float4 id, 4096 total
        int row = vid >> 5, col4 = (vid & 31) * 4;
        float4 v4 = *(const float4*)(xp + row * 128 + col4);
        float* d = &xs[row * 129 + col4];
        d[0] = v4.x; d[1] = v4.y; d[2] = v4.z; d[3] = v4.w;
    }
    float wv[9];
#pragma unroll
    for (int i = 0; i < 9; i++) wv[i] = dw_w[c * 9 + i];
    float bias = dw_b[c];
    __syncthreads();

    int y = t & 127, half = t >> 7;
    int x0 = half * 64;
    float fm = (y > 0)   ? 1.f : 0.f;
    float fp = (y < 127) ? 1.f : 0.f;
    const float* rm = &xs[(y > 0 ? y - 1 : 0) * 129];
    const float* rc = &xs[y * 129];
    const float* rp = &xs[(y < 127 ? y + 1 : 127) * 129];
    float w00 = wv[0]*fm, w01 = wv[1]*fm, w02 = wv[2]*fm;
    float w10 = wv[3],    w11 = wv[4],    w12 = wv[5];
    float w20 = wv[6]*fp, w21 = wv[7]*fp, w22 = wv[8]*fp;

    float pm, pc, pp, cm, cc, cp;
    if (x0 > 0){ pm = rm[x0 - 1]; pc = rc[x0 - 1]; pp = rp[x0 - 1]; }
    else       { pm = 0.f; pc = 0.f; pp = 0.f; }
    cm = rm[x0]; cc = rc[x0]; cp = rp[x0];

    float* orow = vd + ((long)(b * NC + c)) * HWSZ + y * 128 + x0;
    float ob[4];
#pragma unroll
    for (int xi = 0; xi < 64; xi++){
        int xn = x0 + xi + 1;
        float nm, nc, np;
        if (xn < 128){ nm = rm[xn]; nc = rc[xn]; np = rp[xn]; }
        else         { nm = 0.f; nc = 0.f; np = 0.f; }
        float s = bias;
        s += w00 * pm + w01 * cm + w02 * nm;
        s += w10 * pc + w11 * cc + w12 * nc;
        s += w20 * pp + w21 * cp + w22 * np;
        ob[xi & 3] = __uint_as_float(f2tf(fmaxf(s, 0.f)));
        if ((xi & 3) == 3)
            *(float4*)&orow[xi - 3] = make_float4(ob[0], ob[1], ob[2], ob[3]);
        pm = cm; pc = cc; pp = cp;
        cm = nm; cc = nc; cp = np;
    }
}

// ---------------- K4: row inverse norms of q,k heads ----------------
__global__ void k_rownorm(const float* __restrict__ q, const float* __restrict__ k,
                          float* __restrict__ invq, float* __restrict__ invk){
    int gw = (blockIdx.x * blockDim.x + threadIdx.x) >> 5;
    int lane = threadIdx.x & 31;
    int sel = gw >> 13;
    int r = gw & 8191;
    int b = r >> 10; int rem = r & 1023; int h = rem >> 8; int c = rem & 255;
    const float* src = (sel ? k : q) + (long)b * NC * LP + (long)c * LP + h * DH;
    float s = 0.f;
#pragma unroll
    for (int d = lane; d < DH; d += 32){ float v = src[d]; s += v * v; }
    s = warpRedSum(s);
    if (lane == 0){
        float inv = 1.f / fmaxf(sqrtf(s), 1e-12f);
        (sel ? invk : invq)[(b * NHH + h) * 256 + c] = inv;
    }
}

// ---------------- K5: CPB relative position bias ----------------
__global__ void k_cpb(const float* __restrict__ w1, const float* __restrict__ b1,
                      const float* __restrict__ w2, float* __restrict__ biasb){
    __shared__ float s1[64], sb1[64], s2[256];
    int t = threadIdx.x;
    if (t < 64){ s1[t] = w1[t]; sb1[t] = b1[t]; }
    s2[t] = w2[t];
    __syncthreads();
    int idx = blockIdx.x * 256 + t;
    int i = idx >> 8, j = idx & 255;
    float coords = (float)(j - i);
    float rel = coords * (8.0f / 255.0f);
    float sg = (rel > 0.f) ? 1.f : ((rel < 0.f) ? -1.f : 0.f);
    float f = sg * log2f(fabsf(rel) + 1.f) * (1.f / 3.f);
    float o0 = 0.f, o1 = 0.f, o2 = 0.f, o3 = 0.f;
#pragma unroll 8
    for (int h = 0; h < 64; h++){
        float hv = fmaxf(f * s1[h] + sb1[h], 0.f);
        o0 += hv * s2[h * 4 + 0];
        o1 += hv * s2[h * 4 + 1];
        o2 += hv * s2[h * 4 + 2];
        o3 += hv * s2[h * 4 + 3];
    }
    biasb[0 * 65536 + idx] = 1.f / (1.f + expf(-o0));
    biasb[1 * 65536 + idx] = 1.f / (1.f + expf(-o1));
    biasb[2 * 65536 + idx] = 1.f / (1.f + expf(-o2));
    biasb[3 * 65536 + idx] = 1.f / (1.f + expf(-o3));
}

// ---------------- K7: double softmax, warp per row (no barriers) ----------------
__global__ void k_dsoftmax(float* __restrict__ simb){
    int row = blockIdx.x * 8 + (threadIdx.x >> 5);
    int lane = threadIdx.x & 31;
    float* p = simb + (long)row * 256;
    float v[8];
#pragma unroll
    for (int j = 0; j < 8; j++) v[j] = p[lane + 32 * j];
    float m = v[0];
#pragma unroll
    for (int j = 1; j < 8; j++) m = fmaxf(m, v[j]);
    m = warpRedMax(m);
    float s = 0.f;
#pragma unroll
    for (int j = 0; j < 8; j++){ v[j] = expf(v[j] - m); s += v[j]; }
    s = warpRedSum(s);
    float inv = 1.f / s;
    float mn = v[0];
#pragma unroll
    for (int j = 1; j < 8; j++) mn = fminf(mn, v[j]);
    mn = warpRedMin(mn);
    float e2[8]; float s2 = 0.f;
#pragma unroll
    for (int j = 0; j < 8; j++){ e2[j] = expf((mn - v[j]) * inv); s2 += e2[j]; }
    s2 = warpRedSum(s2);
    float i2 = 1.f / s2;
#pragma unroll
    for (int j = 0; j < 8; j++) p[lane + 32 * j] = e2[j] * i2;
}

// ---------------- shared tf32 tile sizes ----------------
#define A_WORDS 4608   // 128*36
#define B_WORDS 4352   // 32*136

// ---- A-side register staging (rna cvt) ----
__device__ __forceinline__ void ldA(const float* __restrict__ Ab, long lda, int kt, int tid, float4* ar){
#pragma unroll
    for (int i = 0; i < 4; i++){
        int vid = tid + i * 256;
        int r = vid >> 3, c4 = (vid & 7) << 2;
        ar[i] = *(const float4*)(Ab + (long)r * lda + kt * 32 + c4);
    }
}
__device__ __forceinline__ void stA(unsigned* As, int tid, const float4* ar){
#pragma unroll
    for (int i = 0; i < 4; i++){
        int vid = tid + i * 256;
        int r = vid >> 3, c4 = (vid & 7) << 2;
        uint4 ua; ua.x = f2tf(ar[i].x); ua.y = f2tf(ar[i].y); ua.z = f2tf(ar[i].z); ua.w = f2tf(ar[i].w);
        *(uint4*)&As[r * 36 + c4] = ua;
    }
}
// ---- B-side (row-major [k][n]) ----
__device__ __forceinline__ void ldB(const float* __restrict__ Bb, long ldb, int kt, int tid, float4* br){
#pragma unroll
    for (int i = 0; i < 4; i++){
        int vid = tid + i * 256;
        int kr = vid >> 5, n4 = (vid & 31) << 2;
        br[i] = *(const float4*)(Bb + (long)(kt * 32 + kr) * ldb + n4);
    }
}
__device__ __forceinline__ void stB(unsigned* Bs, int tid, const float4* br){
#pragma unroll
    for (int i = 0; i < 4; i++){
        int vid = tid + i * 256;
        int kr = vid >> 5, n4 = (vid & 31) << 2;
        uint4 ub; ub.x = f2tf(br[i].x); ub.y = f2tf(br[i].y); ub.z = f2tf(br[i].z); ub.w = f2tf(br[i].w);
        *(uint4*)&Bs[kr * 136 + n4] = ub;
    }
}
// ---- B-side cp.async ----
__device__ __forceinline__ void cpB(const float* __restrict__ Bb, long ldb, int kt, int tid,
                                    unsigned bs_u32){
#pragma unroll
    for (int i = 0; i < 4; i++){
        int vid = tid + i * 256;
        int kr = vid >> 5, n4 = (vid & 31) << 2;
        CP_ASYNC16(bs_u32 + (unsigned)((kr * 136 + n4) * 4),
                   Bb + (long)(kt * 32 + kr) * ldb + n4);
    }
}

__device__ __forceinline__ void compute_tile(const unsigned* As, const unsigned* Bs,
        float acc[4][4][4], int wm, int wn, int gq, int tg){
#pragma unroll
    for (int ks = 0; ks < 4; ks++){
        unsigned af[4][4], bf[4][2];
        int c = ks * 8 + tg;
#pragma unroll
        for (int mt = 0; mt < 4; mt++){
            int r = wm * 64 + mt * 16 + gq;
            af[mt][0] = As[r * 36 + c];
            af[mt][1] = As[(r + 8) * 36 + c];
            af[mt][2] = As[r * 36 + c + 4];
            af[mt][3] = As[(r + 8) * 36 + c + 4];
        }
#pragma unroll
        for (int nt = 0; nt < 4; nt++){
            int cc = wn * 32 + nt * 8 + gq;
            bf[nt][0] = Bs[c * 136 + cc];
            bf[nt][1] = Bs[(c + 4) * 136 + cc];
        }
#pragma unroll
        for (int mt = 0; mt < 4; mt++)
#pragma unroll
            for (int nt = 0; nt < 4; nt++)
                mma8(acc[mt][nt], af[mt][0], af[mt][1], af[mt][2], af[mt][3],
                     bf[nt][0], bf[nt][1]);
    }
}

// ---- register-staged double-buffered GEMM (projsim) ----
__device__ __forceinline__ void gemm_db(const float* __restrict__ Ab,
        const float* __restrict__ Bb, long ldb,
        unsigned* As, unsigned* Bs, float acc[4][4][4], int tid){
    int lane = tid & 31, w = tid >> 5, wm = w & 1, wn = w >> 1;
    int gq = lane >> 2, tg = lane & 3;
    float4 ar[4], br[4];
    ldA(Ab, 256, 0, tid, ar); ldB(Bb, ldb, 0, tid, br);
    stA(As, tid, ar); stB(Bs, tid, br);
    __syncthreads();
#pragma unroll
    for (int kt = 0; kt < 8; kt++){
        int cur = kt & 1;
        if (kt < 7){ ldA(Ab, 256, kt + 1, tid, ar); ldB(Bb, ldb, kt + 1, tid, br); }
        compute_tile(As + cur * A_WORDS, Bs + cur * B_WORDS, acc, wm, wn, gq, tg);
        if (kt < 7){ stA(As + (cur ^ 1) * A_WORDS, tid, ar); stB(Bs + (cur ^ 1) * B_WORDS, tid, br); }
        __syncthreads();
    }
}

// ---- mixed pipeline: A via regs+cvt, B via cp.async (k_fused) ----
__device__ __forceinline__ void gemm_mixed(const float* __restrict__ Ab,
        const float* __restrict__ Bb, long ldb,
        unsigned* As, unsigned* Bs, unsigned bs_u32, float acc[4][4][4], int tid){
    int lane = tid & 31, w = tid >> 5, wm = w & 1, wn = w >> 1;
    int gq = lane >> 2, tg = lane & 3;
    float4 ar[4];
    ldA(Ab, 256, 0, tid, ar);
    cpB(Bb, ldb, 0, tid, bs_u32);
    CP_COMMIT;
    stA(As, tid, ar);
    ldA(Ab, 256, 1, tid, ar);
    CP_WAIT0;
    __syncthreads();
#pragma unroll
    for (int kt = 0; kt < 8; kt++){
        int cur = kt & 1, nxt = cur ^ 1;
        if (kt < 7){
            cpB(Bb, ldb, kt + 1, tid, bs_u32 + (unsigned)(nxt * B_WORDS * 4));
            CP_COMMIT;
        }
        compute_tile(As + cur * A_WORDS, Bs + cur * B_WORDS, acc, wm, wn, gq, tg);
        if (kt < 7){
            stA(As + nxt * A_WORDS, tid, ar);
            if (kt < 6) ldA(Ab, 256, kt + 2, tid, ar);
            CP_WAIT0;
        }
        __syncthreads();
    }
}

// ---------------- K6: sim via tf32 MMA ----------------
__global__ void __launch_bounds__(256)
k_simmma(const float* __restrict__ qb, const float* __restrict__ kb,
         const float* __restrict__ invq, const float* __restrict__ invk,
         const float* __restrict__ ls, const float* __restrict__ biasb,
         float* __restrict__ simb){
    extern __shared__ unsigned smu[];
    unsigned* As  = smu;                 // 2*4608
    unsigned* BsT = smu + 2 * A_WORDS;   // 2*4608
    int tid = threadIdx.x;
    int bz = blockIdx.z;
    int b = bz >> 2, h = bz & 3;
    const float* qbase = qb + (long)b * NC * LP + h * DH + (long)blockIdx.y * 128 * LP;
    const float* kbase = kb + (long)b * NC * LP + h * DH + (long)blockIdx.x * 128 * LP;

    int lane = tid & 31, w = tid >> 5, wm = w & 1, wn = w >> 1;
    int gq = lane >> 2, tg = lane & 3;

    float acc[4][4][4];
#pragma unroll
    for (int mt = 0; mt < 4; mt++)
#pragma unroll
        for (int nt = 0; nt < 4; nt++)
#pragma unroll
            for (int q = 0; q < 4; q++) acc[mt][nt][q] = 0.f;

    float4 ar[4], br[4];
    ldA(qbase, LP, 0, tid, ar); ldA(kbase, LP, 0, tid, br);
    stA(As, tid, ar); stA(BsT, tid, br);
    __syncthreads();
#pragma unroll
    for (int kt = 0; kt < 8; kt++){
        int cur = kt & 1;
        if (kt < 7){ ldA(qbase, LP, kt + 1, tid, ar); ldA(kbase, LP, kt + 1, tid, br); }
        {
            const unsigned* Ac = As + cur * A_WORDS;
            const unsigned* Bc = BsT + cur * A_WORDS;
#pragma unroll
            for (int ks = 0; ks < 4; ks++){
                unsigned af[4][4], bf[4][2];
                int c = ks * 8 + tg;
#pragma unroll
                for (int mt = 0; mt < 4; mt++){
                    int r = wm * 64 + mt * 16 + gq;
                    af[mt][0] = Ac[r * 36 + c];
                    af[mt][1] = Ac[(r + 8) * 36 + c];
                    af[mt][2] = Ac[r * 36 + c + 4];
                    af[mt][3] = Ac[(r + 8) * 36 + c + 4];
                }
#pragma unroll
                for (int nt = 0; nt < 4; nt++){
                    int cc = wn * 32 + nt * 8 + gq;
                    bf[nt][0] = Bc[cc * 36 + c];
                    bf[nt][1] = Bc[cc * 36 + c + 4];
                }
#pragma unroll
                for (int mt = 0; mt < 4; mt++)
#pragma unroll
                    for (int nt = 0; nt < 4; nt++)
                        mma8(acc[mt][nt], af[mt][0], af[mt][1], af[mt][2], af[mt][3],
                             bf[nt][0], bf[nt][1]);
            }
        }
        if (kt < 7){ stA(As + (cur ^ 1) * A_WORDS, tid, ar); stA(BsT + (cur ^ 1) * A_WORDS, tid, br); }
        __syncthreads();
    }

    float scale = expf(fminf(ls[h], 4.6051702f));
    int c0 = blockIdx.y * 128, e0 = blockIdx.x * 128;
    float* Cp = simb + (long)bz * 65536;
#pragma unroll
    for (int mt = 0; mt < 4; mt++){
        int rA = c0 + wm * 64 + mt * 16 + gq, rB = rA + 8;
        float iqA = invq[bz * 256 + rA] * scale;
        float iqB = invq[bz * 256 + rB] * scale;
#pragma unroll
        for (int nt = 0; nt < 4; nt++){
            int col = e0 + wn * 32 + nt * 8 + tg * 2;
            float ik0 = invk[bz * 256 + col], ik1 = invk[bz * 256 + col + 1];
            const float* bb = biasb + h * 65536;
            float2 o0 = make_float2(acc[mt][nt][0] * iqA * ik0 + bb[rA * 256 + col],
                                    acc[mt][nt][1] * iqA * ik1 + bb[rA * 256 + col + 1]);
            float2 o1 = make_float2(acc[mt][nt][2] * iqB * ik0 + bb[rB * 256 + col],
                                    acc[mt][nt][3] * iqB * ik1 + bb[rB * 256 + col + 1]);
            *(float2*)&Cp[(long)rA * 256 + col] = o0;
            *(float2*)&Cp[(long)rB * 256 + col] = o1;
        }
    }
}

// ---------------- K8: msim = proj @ sim  per (b,h) ----------------
__global__ void __launch_bounds__(256)
k_projsim(const float* __restrict__ proj, const float* __restrict__ simb,
          float* __restrict__ msim){
    extern __shared__ unsigned smu[];
    unsigned* As = smu;
    unsigned* Bs = smu + 2 * A_WORDS;
    int tid = threadIdx.x;
    int bz = blockIdx.z;
    const float* Ab = proj + (long)blockIdx.y * 128 * 256;
    const float* Bb = simb + (long)bz * 65536 + blockIdx.x * 128;
    float* C = msim + (long)bz * 65536;

    float acc[4][4][4];
#pragma unroll
    for (int mt = 0; mt < 4; mt++)
#pragma unroll
        for (int nt = 0; nt < 4; nt++)
#pragma unroll
            for (int q = 0; q < 4; q++) acc[mt][nt][q] = 0.f;

    gemm_db(Ab, Bb, 256, As, Bs, acc, tid);

    int lane = tid & 31;
    int w = tid >> 5, wm = w & 1, wn = w >> 1;
    int gq = lane >> 2, tg = lane & 3;
    int m0 = blockIdx.y * 128 + wm * 64;
    int n0 = blockIdx.x * 128 + wn * 32;
#pragma unroll
    for (int mt = 0; mt < 4; mt++){
        int rA = m0 + mt * 16 + gq;
#pragma unroll
        for (int nt = 0; nt < 4; nt++){
            int col = n0 + nt * 8 + tg * 2;
            *(float2*)&C[(long)rA * 256 + col]       = make_float2(acc[mt][nt][0], acc[mt][nt][1]);
            *(float2*)&C[(long)(rA + 8) * 256 + col] = make_float2(acc[mt][nt][2], acc[mt][nt][3]);
        }
    }
}

// ---------------- K8b: fold pw into msim: msim <- msim @ blockdiag(Wpw); mbias = msim@pwb ----
// grid (32), block 256 (thread = row c). In-place safe (row loaded to regs first).
__global__ void __launch_bounds__(256)
k_fold(float* __restrict__ msim, const float* __restrict__ pw_w,
       const float* __restrict__ pw_b, float* __restrict__ mbias){
    __shared__ float Ws[4096];
    __shared__ float pbs[256];
    int bz = blockIdx.x;
    int t = threadIdx.x;
    pbs[t] = pw_b[t];
    float* row = msim + (long)bz * 65536 + (long)t * 256;
    float mb = 0.f;
    for (int g = 0; g < 4; g++){
        __syncthreads();
        for (int i = t; i < 4096; i += 256) Ws[i] = pw_w[g * 4096 + i];
        __syncthreads();
        float a[64];
#pragma unroll
        for (int j = 0; j < 64; j++) a[j] = row[g * 64 + j];
        float acc[64];
#pragma unroll
        for (int j = 0; j < 64; j++) acc[j] = 0.f;
        for (int eo = 0; eo < 64; eo++){
            float av = a[eo];
            mb += av * pbs[g * 64 + eo];
            const float4* wr = (const float4*)(Ws + eo * 64);
#pragma unroll
            for (int i4 = 0; i4 < 16; i4++){
                float4 wv = wr[i4];
                acc[i4*4+0] += av * wv.x;
                acc[i4*4+1] += av * wv.y;
                acc[i4*4+2] += av * wv.z;
                acc[i4*4+3] += av * wv.w;
            }
        }
#pragma unroll
        for (int i4 = 0; i4 < 16; i4++)
            *(float4*)&row[g * 64 + i4 * 4] =
                make_float4(acc[i4*4+0], acc[i4*4+1], acc[i4*4+2], acc[i4*4+3]);
    }
    mbias[bz * 256 + t] = mb;
}

// ---------------- K9: out = gelu(msim_bh@vd + pb + mbias)*bn + relu(sc@x + scb) ----------------
// grid (128, 2, 8). h = blockIdx.x / 32. 128x128 tiles, mixed cp.async pipeline.
__global__ void __launch_bounds__(256)
k_fused(const float* __restrict__ msim, const float* __restrict__ vdbuf,
        const float* __restrict__ scw, const float* __restrict__ xbuf,
        float* __restrict__ Cg,
        const float* __restrict__ pb, const float* __restrict__ gam,
        const float* __restrict__ bet, const float* __restrict__ scb,
        const float* __restrict__ mbias){
    extern __shared__ unsigned smu[];
    unsigned* As = smu;                      // 2 * 4608
    unsigned* Bs = smu + 2 * A_WORDS;        // 2 * 4352
    unsigned bs_u32 = (unsigned)__cvta_generic_to_shared(Bs);
    int tid = threadIdx.x;
    int b = blockIdx.z;
    int h = blockIdx.x >> 5;
    int bz = b * NHH + h;
    const float* A = msim + (long)bz * 65536;
    const float* B = vdbuf + (long)b * NC * HWSZ;
    float* C = Cg + (long)b * NC * HWSZ;

    const float* Ab = A + (long)blockIdx.y * 128 * 256;
    const float* Bb = B + blockIdx.x * 128;

    float acc[4][4][4];
#pragma unroll
    for (int mt = 0; mt < 4; mt++)
#pragma unroll
        for (int nt = 0; nt < 4; nt++)
#pragma unroll
            for (int q = 0; q < 4; q++) acc[mt][nt][q] = 0.f;

    gemm_mixed(Ab, Bb, HWSZ, As, Bs, bs_u32, acc, tid);

    int lane = tid & 31;
    int w = tid >> 5, wm = w & 1, wn = w >> 1;
    int gq = lane >> 2, tg = lane & 3;
    int m0 = blockIdx.y * 128 + wm * 64;
    long n0 = (long)blockIdx.x * 128 + wn * 32;

    const float BNS = 0.9999950000374998f;   // 1/sqrt(1+1e-5)
    const float ISQ2 = 0.70710678118654752f;
    float res[4][4][4];
#pragma unroll
    for (int mt = 0; mt < 4; mt++){
        int rA = m0 + mt * 16 + gq, rB = rA + 8;
        float pbA = pb[rA] + mbias[bz * 256 + rA];
        float pbB = pb[rB] + mbias[bz * 256 + rB];
        float gaA = gam[rA] * BNS, gaB = gam[rB] * BNS;
        float beA = bet[rA], beB = bet[rB];
#pragma unroll
        for (int nt = 0; nt < 4; nt++){
            float z;
            z = acc[mt][nt][0] + pbA; res[mt][nt][0] = 0.5f*z*(1.f+erff(z*ISQ2))*gaA + beA;
            z = acc[mt][nt][1] + pbA; res[mt][nt][1] = 0.5f*z*(1.f+erff(z*ISQ2))*gaA + beA;
            z = acc[mt][nt][2] + pbB; res[mt][nt][2] = 0.5f*z*(1.f+erff(z*ISQ2))*gaB + beB;
            z = acc[mt][nt][3] + pbB; res[mt][nt][3] = 0.5f*z*(1.f+erff(z*ISQ2))*gaB + beB;
        }
    }
#pragma unroll
    for (int mt = 0; mt < 4; mt++)
#pragma unroll
        for (int nt = 0; nt < 4; nt++)
#pragma unroll
            for (int q = 0; q < 4; q++) acc[mt][nt][q] = 0.f;
    __syncthreads();

    gemm_mixed(scw + (long)blockIdx.y * 128 * 256,
               xbuf + (long)b * NC * HWSZ + blockIdx.x * 128,
               HWSZ, As, Bs, bs_u32, acc, tid);
#pragma unroll
    for (int mt = 0; mt < 4; mt++){
        int rA = m0 + mt * 16 + gq, rB = rA + 8;
        float sA = scb[rA], sB = scb[rB];
#pragma unroll
        for (int nt = 0; nt < 4; nt++){
            long col = n0 + nt * 8 + tg * 2;
            float2 o0 = make_float2(res[mt][nt][0] + fmaxf(acc[mt][nt][0] + sA, 0.f),
                                    res[mt][nt][1] + fmaxf(acc[mt][nt][1] + sA, 0.f));
            float2 o1 = make_float2(res[mt][nt][2] + fmaxf(acc[mt][nt][2] + sB, 0.f),
                                    res[mt][nt][3] + fmaxf(acc[mt][nt][3] + sB, 0.f));
            *(float2*)&C[(long)rA * HWSZ + col] = o0;
            *(float2*)&C[(long)rB * HWSZ + col] = o1;
        }
    }
}

// ---------------- launch ----------------
extern "C" void kernel_launch(void* const* d_in, const int* in_sizes, int n_in,
                              void* d_out, int out_size){
    const float* x        = (const float*)d_in[0];
    const float* sc_w     = (const float*)d_in[1];
    const float* sc_b     = (const float*)d_in[2];
    const float* q_w      = (const float*)d_in[3];
    const float* q_b      = (const float*)d_in[4];
    const float* k_w      = (const float*)d_in[5];
    const float* k_b      = (const float*)d_in[6];
    const float* v_dw_w   = (const float*)d_in[7];
    const float* v_dw_b   = (const float*)d_in[8];
    const float* v_pw_w   = (const float*)d_in[9];
    const float* v_pw_b   = (const float*)d_in[10];
    const float* logit_sc = (const float*)d_in[11];
    const float* cpb_w1   = (const float*)d_in[12];
    const float* cpb_b1   = (const float*)d_in[13];
    const float* cpb_w2   = (const float*)d_in[14];
    const float* proj_w   = (const float*)d_in[15];
    const float* proj_b   = (const float*)d_in[16];
    const float* bn_gamma = (const float*)d_in[17];
    const float* bn_beta  = (const float*)d_in[18];
    float* out = (float*)d_out;

    float *xp, *qb, *kb, *vd, *sim, *msim, *biasb, *invq, *invk, *mbias;
    cudaGetSymbolAddress((void**)&xp,   g_xp);
    cudaGetSymbolAddress((void**)&qb,   g_q);
    cudaGetSymbolAddress((void**)&kb,   g_k);
    cudaGetSymbolAddress((void**)&vd,   g_v);
    cudaGetSymbolAddress((void**)&sim,  g_sim);
    cudaGetSymbolAddress((void**)&msim, g_msim);
    cudaGetSymbolAddress((void**)&biasb,g_bias);
    cudaGetSymbolAddress((void**)&invq, g_invq);
    cudaGetSymbolAddress((void**)&invk, g_invk);
    cudaGetSymbolAddress((void**)&mbias,g_mbias);

    const int dw_smem    = 128 * 129 * 4;                          // 66048
    const int mma_smem   = 2 * (A_WORDS + B_WORDS) * 4;            // 71680
    const int sim_smem   = 4 * A_WORDS * 4;                        // 73728
    cudaFuncSetAttribute(k_dw,      cudaFuncAttributeMaxDynamicSharedMemorySize, dw_smem);
    cudaFuncSetAttribute(k_projsim, cudaFuncAttributeMaxDynamicSharedMemorySize, mma_smem);
    cudaFuncSetAttribute(k_fused,   cudaFuncAttributeMaxDynamicSharedMemorySize, mma_smem);
    cudaFuncSetAttribute(k_simmma,  cudaFuncAttributeMaxDynamicSharedMemorySize, sim_smem);

    // 1. maxpool 4x4  x -> xp
    k_maxpool<<<(NB*NC*LP)/256, 256>>>(x, xp);
    // 2/3. q,k grouped pw on pooled
    k_grouped_pw<<<dim3(LP/128, NG, NB), 128>>>(xp, q_w, q_b, qb, LP);
    k_grouped_pw<<<dim3(LP/128, NG, NB), 128>>>(xp, k_w, k_b, kb, LP);
    // 4. depthwise 3x3 + relu: x -> vd  [profiled slot]
    k_dw<<<dim3(NC, NB), 256, dw_smem>>>(x, v_dw_w, v_dw_b, vd);
    // 5. inverse row norms
    k_rownorm<<<2048, 256>>>(qb, kb, invq, invk);
    // 6. CPB bias table
    k_cpb<<<256, 256>>>(cpb_w1, cpb_b1, cpb_w2, biasb);
    // 7. sim GEMM (tf32 mma) + scale + bias
    k_simmma<<<dim3(2, 2, NB*NHH), 256, sim_smem>>>(qb, kb, invq, invk, logit_sc, biasb, sim);
    // 8. double softmax (warp per row)
    k_dsoftmax<<<1024, 256>>>(sim);
    // 9. msim = proj @ sim per (b,h)
    k_projsim<<<dim3(2, 2, NB*NHH), 256, mma_smem>>>(proj_w, sim, msim);
    // 10. fold pw conv into msim (in place) + mbias
    k_fold<<<NB*NHH, 256>>>(msim, v_pw_w, v_pw_b, mbias);
    // 11. out = gelu(msim@vd + pb + mbias)*bn + relu(sc@x + scb)
    k_fused<<<dim3(HWSZ/128, 2, NB), 256, mma_smem>>>(msim, vd, sc_w, x, out,
                                                      proj_b, bn_gamma, bn_beta, sc_b, mbias);
}

// round 15
// speedup vs baseline: 1.1816x; 1.1816x over previous
#include <cuda_runtime.h>
#include <cuda_fp16.h>
#include <math.h>

// ---------------- problem constants ----------------
#define NB   8
#define NC   256
#define NG   4
#define CG   64
#define NHH  4
#define WW   128
#define HWSZ 16384        // 128*128
#define LP   1024         // pooled spatial (32*32)
#define DH   256          // LP/NH
#define DV   4096         // HW/NH

// ---------------- scratch ----------------
__device__ float  g_xp [NB*NC*LP];
__device__ float  g_q  [NB*NC*LP];
__device__ float  g_k  [NB*NC*LP];
__device__ __half g_vh [NB*NC*HWSZ];         // dw output (half)
__device__ __half g_xh [NB*NC*HWSZ];         // x converted to half
__device__ float  g_sim[NB*NHH*256*256];
__device__ float  g_msim[NB*NHH*256*256];
__device__ __half g_msimh[NB*NHH*256*256];   // folded msim (half)
__device__ __half g_scwh[256*256];           // sc_w (half)
__device__ float  g_bias[NHH*256*256];
__device__ float  g_invq[NB*NHH*256];
__device__ float  g_invk[NB*NHH*256];
__device__ float  g_mbias[NB*NHH*256];

// ---------------- helpers ----------------
__device__ __forceinline__ float warpRedSum(float v){
#pragma unroll
    for (int o = 16; o > 0; o >>= 1) v += __shfl_xor_sync(0xffffffffu, v, o);
    return v;
}
__device__ __forceinline__ float warpRedMax(float v){
#pragma unroll
    for (int o = 16; o > 0; o >>= 1) v = fmaxf(v, __shfl_xor_sync(0xffffffffu, v, o));
    return v;
}
__device__ __forceinline__ float warpRedMin(float v){
#pragma unroll
    for (int o = 16; o > 0; o >>= 1) v = fminf(v, __shfl_xor_sync(0xffffffffu, v, o));
    return v;
}
__device__ __forceinline__ unsigned f2tf(float f){
    unsigned u; asm("cvt.rna.tf32.f32 %0, %1;" : "=r"(u) : "f"(f)); return u;
}
__device__ __forceinline__ void mma8(float* c, unsigned a0, unsigned a1, unsigned a2, unsigned a3,
                                     unsigned b0, unsigned b1){
    asm volatile("mma.sync.aligned.m16n8k8.row.col.f32.tf32.tf32.f32 "
                 "{%0,%1,%2,%3},{%4,%5,%6,%7},{%8,%9},{%0,%1,%2,%3};"
                 : "+f"(c[0]), "+f"(c[1]), "+f"(c[2]), "+f"(c[3])
                 : "r"(a0), "r"(a1), "r"(a2), "r"(a3), "r"(b0), "r"(b1));
}
__device__ __forceinline__ void mma16h(float* c, unsigned a0, unsigned a1, unsigned a2, unsigned a3,
                                       unsigned b0, unsigned b1){
    asm volatile("mma.sync.aligned.m16n8k16.row.col.f32.f16.f16.f32 "
                 "{%0,%1,%2,%3},{%4,%5,%6,%7},{%8,%9},{%0,%1,%2,%3};"
                 : "+f"(c[0]), "+f"(c[1]), "+f"(c[2]), "+f"(c[3])
                 : "r"(a0), "r"(a1), "r"(a2), "r"(a3), "r"(b0), "r"(b1));
}
#define CP_ASYNC16(saddr, gptr) \
    asm volatile("cp.async.cg.shared.global [%0], [%1], 16;" :: "r"(saddr), "l"(gptr))
#define CP_COMMIT  asm volatile("cp.async.commit_group;")
#define CP_WAIT0   asm volatile("cp.async.wait_group 0;")

// ---------------- K1: 4x4 maxpool + x->half conversion ----------------
__global__ void k_maxpool(const float* __restrict__ xin, float* __restrict__ out,
                          __half* __restrict__ xh){
    int idx = blockIdx.x * 256 + threadIdx.x;
    int pp = idx & 1023;
    int bc = idx >> 10;
    int ph = pp >> 5, pw = pp & 31;
    const float* xp = xin + (long)bc * HWSZ + (ph * 4) * WW + pw * 4;
    __half* xhp = xh + (long)bc * HWSZ + (ph * 4) * WW + pw * 4;
    float m = -3.4e38f;
#pragma unroll
    for (int i = 0; i < 4; i++){
        float4 v4 = *(const float4*)(xp + i * WW);
        m = fmaxf(m, fmaxf(fmaxf(v4.x, v4.y), fmaxf(v4.z, v4.w)));
        __half2 h0 = __floats2half2_rn(v4.x, v4.y);
        __half2 h1 = __floats2half2_rn(v4.z, v4.w);
        *(__half2*)(xhp + i * WW)     = h0;
        *(__half2*)(xhp + i * WW + 2) = h1;
    }
    out[idx] = m;
}

// ---------------- K2: grouped 1x1 pw conv (pooled q/k path) ----------------
__global__ void k_grouped_pw(const float* __restrict__ in, const float* __restrict__ w,
                             const float* __restrict__ bias, float* __restrict__ out, int L){
    __shared__ float wsT[64 * 64];
    __shared__ float xs[64][128];
    int g = blockIdx.y, b = blockIdx.z;
    int l0 = blockIdx.x * 128;
    int t = threadIdx.x;
    for (int idx = t; idx < 4096; idx += 128){
        int i = idx >> 6, j = idx & 63;
        wsT[j * 64 + i] = w[g * 4096 + idx];
    }
    const float* ip = in + ((long)(b * NC + g * CG)) * L + l0;
#pragma unroll 8
    for (int j = 0; j < 64; j++) xs[j][t] = ip[(long)j * L + t];
    __syncthreads();
    float acc[64];
#pragma unroll
    for (int i = 0; i < 64; i++) acc[i] = 0.f;
#pragma unroll 4
    for (int j = 0; j < 64; j++){
        float xv = xs[j][t];
        const float4* wr = (const float4*)(wsT + j * 64);
#pragma unroll
        for (int i4 = 0; i4 < 16; i4++){
            float4 wv = wr[i4];
            acc[i4*4+0] += wv.x * xv;
            acc[i4*4+1] += wv.y * xv;
            acc[i4*4+2] += wv.z * xv;
            acc[i4*4+3] += wv.w * xv;
        }
    }
    float* op = out + ((long)(b * NC + g * CG)) * L + l0;
#pragma unroll 8
    for (int i = 0; i < 64; i++)
        op[(long)i * L + t] = acc[i] + bias[g * CG + i];
}

// ---------------- K3: depthwise 3x3 + relu -> half ----------------
__global__ void __launch_bounds__(256)
k_dw(const float* __restrict__ x, const float* __restrict__ dw_w,
     const float* __restrict__ dw_b, __half* __restrict__ vd){
    extern __shared__ float xs[];          // 128*129 floats
    int c = blockIdx.x, b = blockIdx.y;
    const float* xp = x + ((long)(b * NC + c)) * HWSZ;
    int t = threadIdx.x;

#pragma unroll
    for (int i = 0; i < 16; i++){
        int vid = t + i * 256;
        int row = vid >> 5, col4 = (vid & 31) * 4;
        float4 v4 = *(const float4*)(xp + row * 128 + col4);
        float* d = &xs[row * 129 + col4];
        d[0] = v4.x; d[1] = v4.y; d[2] = v4.z; d[3] = v4.w;
    }
    float wv[9];
#pragma unroll
    for (int i = 0; i < 9; i++) wv[i] = dw_w[c * 9 + i];
    float bias = dw_b[c];
    __syncthreads();

    int y = t & 127, half = t >> 7;
    int x0 = half * 64;
    float fm = (y > 0)   ? 1.f : 0.f;
    float fp = (y < 127) ? 1.f : 0.f;
    const float* rm = &xs[(y > 0 ? y - 1 : 0) * 129];
    const float* rc = &xs[y * 129];
    const float* rp = &xs[(y < 127 ? y + 1 : 127) * 129];
    float w00 = wv[0]*fm, w01 = wv[1]*fm, w02 = wv[2]*fm;
    float w10 = wv[3],    w11 = wv[4],    w12 = wv[5];
    float w20 = wv[6]*fp, w21 = wv[7]*fp, w22 = wv[8]*fp;

    float pm, pc, pp, cm, cc, cp;
    if (x0 > 0){ pm = rm[x0 - 1]; pc = rc[x0 - 1]; pp = rp[x0 - 1]; }
    else       { pm = 0.f; pc = 0.f; pp = 0.f; }
    cm = rm[x0]; cc = rc[x0]; cp = rp[x0];

    __half* orow = vd + ((long)(b * NC + c)) * HWSZ + y * 128 + x0;
    __align__(16) __half ob[8];
#pragma unroll
    for (int xi = 0; xi < 64; xi++){
        int xn = x0 + xi + 1;
        float nm, nc, np;
        if (xn < 128){ nm = rm[xn]; nc = rc[xn]; np = rp[xn]; }
        else         { nm = 0.f; nc = 0.f; np = 0.f; }
        float s = bias;
        s += w00 * pm + w01 * cm + w02 * nm;
        s += w10 * pc + w11 * cc + w12 * nc;
        s += w20 * pp + w21 * cp + w22 * np;
        ob[xi & 7] = __float2half(fmaxf(s, 0.f));
        if ((xi & 7) == 7)
            *(uint4*)&orow[xi - 7] = *(const uint4*)ob;
        pm = cm; pc = cc; pp = cp;
        cm = nm; cc = nc; cp = np;
    }
}

// ---------------- K4: row inverse norms of q,k heads ----------------
__global__ void k_rownorm(const float* __restrict__ q, const float* __restrict__ k,
                          float* __restrict__ invq, float* __restrict__ invk){
    int gw = (blockIdx.x * blockDim.x + threadIdx.x) >> 5;
    int lane = threadIdx.x & 31;
    int sel = gw >> 13;
    int r = gw & 8191;
    int b = r >> 10; int rem = r & 1023; int h = rem >> 8; int c = rem & 255;
    const float* src = (sel ? k : q) + (long)b * NC * LP + (long)c * LP + h * DH;
    float s = 0.f;
#pragma unroll
    for (int d = lane; d < DH; d += 32){ float v = src[d]; s += v * v; }
    s = warpRedSum(s);
    if (lane == 0){
        float inv = 1.f / fmaxf(sqrtf(s), 1e-12f);
        (sel ? invk : invq)[(b * NHH + h) * 256 + c] = inv;
    }
}

// ---------------- K4b: sc_w -> half ----------------
__global__ void k_whalf(const float* __restrict__ w, __half* __restrict__ wh){
    int i = blockIdx.x * 256 + threadIdx.x;
    wh[i] = __float2half(w[i]);
}

// ---------------- K5: CPB relative position bias ----------------
__global__ void k_cpb(const float* __restrict__ w1, const float* __restrict__ b1,
                      const float* __restrict__ w2, float* __restrict__ biasb){
    __shared__ float s1[64], sb1[64], s2[256];
    int t = threadIdx.x;
    if (t < 64){ s1[t] = w1[t]; sb1[t] = b1[t]; }
    s2[t] = w2[t];
    __syncthreads();
    int idx = blockIdx.x * 256 + t;
    int i = idx >> 8, j = idx & 255;
    float coords = (float)(j - i);
    float rel = coords * (8.0f / 255.0f);
    float sg = (rel > 0.f) ? 1.f : ((rel < 0.f) ? -1.f : 0.f);
    float f = sg * log2f(fabsf(rel) + 1.f) * (1.f / 3.f);
    float o0 = 0.f, o1 = 0.f, o2 = 0.f, o3 = 0.f;
#pragma unroll 8
    for (int h = 0; h < 64; h++){
        float hv = fmaxf(f * s1[h] + sb1[h], 0.f);
        o0 += hv * s2[h * 4 + 0];
        o1 += hv * s2[h * 4 + 1];
        o2 += hv * s2[h * 4 + 2];
        o3 += hv * s2[h * 4 + 3];
    }
    biasb[0 * 65536 + idx] = 1.f / (1.f + expf(-o0));
    biasb[1 * 65536 + idx] = 1.f / (1.f + expf(-o1));
    biasb[2 * 65536 + idx] = 1.f / (1.f + expf(-o2));
    biasb[3 * 65536 + idx] = 1.f / (1.f + expf(-o3));
}

// ---------------- K7: double softmax, warp per row ----------------
__global__ void k_dsoftmax(float* __restrict__ simb){
    int row = blockIdx.x * 8 + (threadIdx.x >> 5);
    int lane = threadIdx.x & 31;
    float* p = simb + (long)row * 256;
    float v[8];
#pragma unroll
    for (int j = 0; j < 8; j++) v[j] = p[lane + 32 * j];
    float m = v[0];
#pragma unroll
    for (int j = 1; j < 8; j++) m = fmaxf(m, v[j]);
    m = warpRedMax(m);
    float s = 0.f;
#pragma unroll
    for (int j = 0; j < 8; j++){ v[j] = expf(v[j] - m); s += v[j]; }
    s = warpRedSum(s);
    float inv = 1.f / s;
    float mn = v[0];
#pragma unroll
    for (int j = 1; j < 8; j++) mn = fminf(mn, v[j]);
    mn = warpRedMin(mn);
    float e2[8]; float s2 = 0.f;
#pragma unroll
    for (int j = 0; j < 8; j++){ e2[j] = expf((mn - v[j]) * inv); s2 += e2[j]; }
    s2 = warpRedSum(s2);
    float i2 = 1.f / s2;
#pragma unroll
    for (int j = 0; j < 8; j++) p[lane + 32 * j] = e2[j] * i2;
}

// ---------------- tf32 tile helpers (simmma / projsim) ----------------
#define A_WORDS 4608   // 128*36
#define B_WORDS 4352   // 32*136

__device__ __forceinline__ void ldA(const float* __restrict__ Ab, long lda, int kt, int tid, float4* ar){
#pragma unroll
    for (int i = 0; i < 4; i++){
        int vid = tid + i * 256;
        int r = vid >> 3, c4 = (vid & 7) << 2;
        ar[i] = *(const float4*)(Ab + (long)r * lda + kt * 32 + c4);
    }
}
__device__ __forceinline__ void stA(unsigned* As, int tid, const float4* ar){
#pragma unroll
    for (int i = 0; i < 4; i++){
        int vid = tid + i * 256;
        int r = vid >> 3, c4 = (vid & 7) << 2;
        uint4 ua; ua.x = f2tf(ar[i].x); ua.y = f2tf(ar[i].y); ua.z = f2tf(ar[i].z); ua.w = f2tf(ar[i].w);
        *(uint4*)&As[r * 36 + c4] = ua;
    }
}
__device__ __forceinline__ void ldB(const float* __restrict__ Bb, long ldb, int kt, int tid, float4* br){
#pragma unroll
    for (int i = 0; i < 4; i++){
        int vid = tid + i * 256;
        int kr = vid >> 5, n4 = (vid & 31) << 2;
        br[i] = *(const float4*)(Bb + (long)(kt * 32 + kr) * ldb + n4);
    }
}
__device__ __forceinline__ void stB(unsigned* Bs, int tid, const float4* br){
#pragma unroll
    for (int i = 0; i < 4; i++){
        int vid = tid + i * 256;
        int kr = vid >> 5, n4 = (vid & 31) << 2;
        uint4 ub; ub.x = f2tf(br[i].x); ub.y = f2tf(br[i].y); ub.z = f2tf(br[i].z); ub.w = f2tf(br[i].w);
        *(uint4*)&Bs[kr * 136 + n4] = ub;
    }
}
__device__ __forceinline__ void compute_tile(const unsigned* As, const unsigned* Bs,
        float acc[4][4][4], int wm, int wn, int gq, int tg){
#pragma unroll
    for (int ks = 0; ks < 4; ks++){
        unsigned af[4][4], bf[4][2];
        int c = ks * 8 + tg;
#pragma unroll
        for (int mt = 0; mt < 4; mt++){
            int r = wm * 64 + mt * 16 + gq;
            af[mt][0] = As[r * 36 + c];
            af[mt][1] = As[(r + 8) * 36 + c];
            af[mt][2] = As[r * 36 + c + 4];
            af[mt][3] = As[(r + 8) * 36 + c + 4];
        }
#pragma unroll
        for (int nt = 0; nt < 4; nt++){
            int cc = wn * 32 + nt * 8 + gq;
            bf[nt][0] = Bs[c * 136 + cc];
            bf[nt][1] = Bs[(c + 4) * 136 + cc];
        }
#pragma unroll
        for (int mt = 0; mt < 4; mt++)
#pragma unroll
            for (int nt = 0; nt < 4; nt++)
                mma8(acc[mt][nt], af[mt][0], af[mt][1], af[mt][2], af[mt][3],
                     bf[nt][0], bf[nt][1]);
    }
}
__device__ __forceinline__ void gemm_db(const float* __restrict__ Ab,
        const float* __restrict__ Bb, long ldb,
        unsigned* As, unsigned* Bs, float acc[4][4][4], int tid){
    int lane = tid & 31, w = tid >> 5, wm = w & 1, wn = w >> 1;
    int gq = lane >> 2, tg = lane & 3;
    float4 ar[4], br[4];
    ldA(Ab, 256, 0, tid, ar); ldB(Bb, ldb, 0, tid, br);
    stA(As, tid, ar); stB(Bs, tid, br);
    __syncthreads();
#pragma unroll
    for (int kt = 0; kt < 8; kt++){
        int cur = kt & 1;
        if (kt < 7){ ldA(Ab, 256, kt + 1, tid, ar); ldB(Bb, ldb, kt + 1, tid, br); }
        compute_tile(As + cur * A_WORDS, Bs + cur * B_WORDS, acc, wm, wn, gq, tg);
        if (kt < 7){ stA(As + (cur ^ 1) * A_WORDS, tid, ar); stB(Bs + (cur ^ 1) * B_WORDS, tid, br); }
        __syncthreads();
    }
}

// ---------------- K6: sim via tf32 MMA ----------------
__global__ void __launch_bounds__(256)
k_simmma(const float* __restrict__ qb, const float* __restrict__ kb,
         const float* __restrict__ invq, const float* __restrict__ invk,
         const float* __restrict__ ls, const float* __restrict__ biasb,
         float* __restrict__ simb){
    extern __shared__ unsigned smu[];
    unsigned* As  = smu;
    unsigned* BsT = smu + 2 * A_WORDS;
    int tid = threadIdx.x;
    int bz = blockIdx.z;
    int b = bz >> 2, h = bz & 3;
    const float* qbase = qb + (long)b * NC * LP + h * DH + (long)blockIdx.y * 128 * LP;
    const float* kbase = kb + (long)b * NC * LP + h * DH + (long)blockIdx.x * 128 * LP;

    int lane = tid & 31, w = tid >> 5, wm = w & 1, wn = w >> 1;
    int gq = lane >> 2, tg = lane & 3;

    float acc[4][4][4];
#pragma unroll
    for (int mt = 0; mt < 4; mt++)
#pragma unroll
        for (int nt = 0; nt < 4; nt++)
#pragma unroll
            for (int q = 0; q < 4; q++) acc[mt][nt][q] = 0.f;

    float4 ar[4], br[4];
    ldA(qbase, LP, 0, tid, ar); ldA(kbase, LP, 0, tid, br);
    stA(As, tid, ar); stA(BsT, tid, br);
    __syncthreads();
#pragma unroll
    for (int kt = 0; kt < 8; kt++){
        int cur = kt & 1;
        if (kt < 7){ ldA(qbase, LP, kt + 1, tid, ar); ldA(kbase, LP, kt + 1, tid, br); }
        {
            const unsigned* Ac = As + cur * A_WORDS;
            const unsigned* Bc = BsT + cur * A_WORDS;
#pragma unroll
            for (int ks = 0; ks < 4; ks++){
                unsigned af[4][4], bf[4][2];
                int c = ks * 8 + tg;
#pragma unroll
                for (int mt = 0; mt < 4; mt++){
                    int r = wm * 64 + mt * 16 + gq;
                    af[mt][0] = Ac[r * 36 + c];
                    af[mt][1] = Ac[(r + 8) * 36 + c];
                    af[mt][2] = Ac[r * 36 + c + 4];
                    af[mt][3] = Ac[(r + 8) * 36 + c + 4];
                }
#pragma unroll
                for (int nt = 0; nt < 4; nt++){
                    int cc = wn * 32 + nt * 8 + gq;
                    bf[nt][0] = Bc[cc * 36 + c];
                    bf[nt][1] = Bc[cc * 36 + c + 4];
                }
#pragma unroll
                for (int mt = 0; mt < 4; mt++)
#pragma unroll
                    for (int nt = 0; nt < 4; nt++)
                        mma8(acc[mt][nt], af[mt][0], af[mt][1], af[mt][2], af[mt][3],
                             bf[nt][0], bf[nt][1]);
            }
        }
        if (kt < 7){ stA(As + (cur ^ 1) * A_WORDS, tid, ar); stA(BsT + (cur ^ 1) * A_WORDS, tid, br); }
        __syncthreads();
    }

    float scale = expf(fminf(ls[h], 4.6051702f));
    int c0 = blockIdx.y * 128, e0 = blockIdx.x * 128;
    float* Cp = simb + (long)bz * 65536;
#pragma unroll
    for (int mt = 0; mt < 4; mt++){
        int rA = c0 + wm * 64 + mt * 16 + gq, rB = rA + 8;
        float iqA = invq[bz * 256 + rA] * scale;
        float iqB = invq[bz * 256 + rB] * scale;
#pragma unroll
        for (int nt = 0; nt < 4; nt++){
            int col = e0 + wn * 32 + nt * 8 + tg * 2;
            float ik0 = invk[bz * 256 + col], ik1 = invk[bz * 256 + col + 1];
            const float* bb = biasb + h * 65536;
            float2 o0 = make_float2(acc[mt][nt][0] * iqA * ik0 + bb[rA * 256 + col],
                                    acc[mt][nt][1] * iqA * ik1 + bb[rA * 256 + col + 1]);
            float2 o1 = make_float2(acc[mt][nt][2] * iqB * ik0 + bb[rB * 256 + col],
                                    acc[mt][nt][3] * iqB * ik1 + bb[rB * 256 + col + 1]);
            *(float2*)&Cp[(long)rA * 256 + col] = o0;
            *(float2*)&Cp[(long)rB * 256 + col] = o1;
        }
    }
}

// ---------------- K8: msim = proj @ sim  per (b,h) ----------------
__global__ void __launch_bounds__(256)
k_projsim(const float* __restrict__ proj, const float* __restrict__ simb,
          float* __restrict__ msim){
    extern __shared__ unsigned smu[];
    unsigned* As = smu;
    unsigned* Bs = smu + 2 * A_WORDS;
    int tid = threadIdx.x;
    int bz = blockIdx.z;
    const float* Ab = proj + (long)blockIdx.y * 128 * 256;
    const float* Bb = simb + (long)bz * 65536 + blockIdx.x * 128;
    float* C = msim + (long)bz * 65536;

    float acc[4][4][4];
#pragma unroll
    for (int mt = 0; mt < 4; mt++)
#pragma unroll
        for (int nt = 0; nt < 4; nt++)
#pragma unroll
            for (int q = 0; q < 4; q++) acc[mt][nt][q] = 0.f;

    gemm_db(Ab, Bb, 256, As, Bs, acc, tid);

    int lane = tid & 31;
    int w = tid >> 5, wm = w & 1, wn = w >> 1;
    int gq = lane >> 2, tg = lane & 3;
    int m0 = blockIdx.y * 128 + wm * 64;
    int n0 = blockIdx.x * 128 + wn * 32;
#pragma unroll
    for (int mt = 0; mt < 4; mt++){
        int rA = m0 + mt * 16 + gq;
#pragma unroll
        for (int nt = 0; nt < 4; nt++){
            int col = n0 + nt * 8 + tg * 2;
            *(float2*)&C[(long)rA * 256 + col]       = make_float2(acc[mt][nt][0], acc[mt][nt][1]);
            *(float2*)&C[(long)(rA + 8) * 256 + col] = make_float2(acc[mt][nt][2], acc[mt][nt][3]);
        }
    }
}

// ---------------- K8b: fold pw into msim -> half; mbias ----------------
__global__ void __launch_bounds__(256)
k_fold(const float* __restrict__ msim, const float* __restrict__ pw_w,
       const float* __restrict__ pw_b, __half* __restrict__ msimh,
       float* __restrict__ mbias){
    __shared__ float Ws[4096];
    __shared__ float pbs[256];
    int bz = blockIdx.x;
    int t = threadIdx.x;
    pbs[t] = pw_b[t];
    const float* row = msim + (long)bz * 65536 + (long)t * 256;
    __half* rowh = msimh + (long)bz * 65536 + (long)t * 256;
    float mb = 0.f;
    for (int g = 0; g < 4; g++){
        __syncthreads();
        for (int i = t; i < 4096; i += 256) Ws[i] = pw_w[g * 4096 + i];
        __syncthreads();
        float a[64];
#pragma unroll
        for (int j = 0; j < 64; j++) a[j] = row[g * 64 + j];
        float acc[64];
#pragma unroll
        for (int j = 0; j < 64; j++) acc[j] = 0.f;
        for (int eo = 0; eo < 64; eo++){
            float av = a[eo];
            mb += av * pbs[g * 64 + eo];
            const float4* wr = (const float4*)(Ws + eo * 64);
#pragma unroll
            for (int i4 = 0; i4 < 16; i4++){
                float4 wv = wr[i4];
                acc[i4*4+0] += av * wv.x;
                acc[i4*4+1] += av * wv.y;
                acc[i4*4+2] += av * wv.z;
                acc[i4*4+3] += av * wv.w;
            }
        }
#pragma unroll
        for (int j2 = 0; j2 < 32; j2++)
            *(__half2*)&rowh[g * 64 + j2 * 2] = __floats2half2_rn(acc[j2*2], acc[j2*2+1]);
    }
    mbias[bz * 256 + t] = mb;
}

// ---------------- fp16 GEMM core for k_fused ----------------
#define AH_PITCH 40           // halves per A row
#define AH_HALF  (128*40)     // 5120 halves/stage
#define BH_PITCH 136          // halves per B row
#define BH_HALF  (32*136)     // 4352 halves/stage

__device__ __forceinline__ void cpAh(const __half* __restrict__ Ab, long lda, int kt, int tid,
                                     unsigned as_u32){
#pragma unroll
    for (int i = 0; i < 2; i++){
        int u = tid + i * 256;
        int r = u >> 2, c8 = (u & 3) * 8;
        CP_ASYNC16(as_u32 + (unsigned)((r * AH_PITCH + c8) * 2),
                   Ab + (long)r * lda + kt * 32 + c8);
    }
}
__device__ __forceinline__ void cpBh(const __half* __restrict__ Bb, long ldb, int kt, int tid,
                                     unsigned bs_u32){
#pragma unroll
    for (int i = 0; i < 2; i++){
        int u = tid + i * 256;
        int kr = u >> 4, n8 = (u & 15) * 8;
        CP_ASYNC16(bs_u32 + (unsigned)((kr * BH_PITCH + n8) * 2),
                   Bb + (long)(kt * 32 + kr) * ldb + n8);
    }
}
__device__ __forceinline__ void compute_tile_h(const __half* Ah, const __half* Bh,
        float acc[4][4][4], int wm, int wn, int gq, int tg){
    const unsigned* Aw = (const unsigned*)Ah;
#pragma unroll
    for (int ks = 0; ks < 2; ks++){
        int c2 = ks * 16 + tg * 2;
        unsigned af[4][4], bf[4][2];
#pragma unroll
        for (int mt = 0; mt < 4; mt++){
            int r = wm * 64 + mt * 16 + gq;
            af[mt][0] = Aw[(r * AH_PITCH + c2) >> 1];
            af[mt][1] = Aw[((r + 8) * AH_PITCH + c2) >> 1];
            af[mt][2] = Aw[(r * AH_PITCH + c2 + 8) >> 1];
            af[mt][3] = Aw[((r + 8) * AH_PITCH + c2 + 8) >> 1];
        }
#pragma unroll
        for (int nt = 0; nt < 4; nt++){
            int cc = wn * 32 + nt * 8 + gq;
            unsigned lo0 = __half_as_ushort(Bh[c2 * BH_PITCH + cc]);
            unsigned hi0 = __half_as_ushort(Bh[(c2 + 1) * BH_PITCH + cc]);
            unsigned lo1 = __half_as_ushort(Bh[(c2 + 8) * BH_PITCH + cc]);
            unsigned hi1 = __half_as_ushort(Bh[(c2 + 9) * BH_PITCH + cc]);
            bf[nt][0] = lo0 | (hi0 << 16);
            bf[nt][1] = lo1 | (hi1 << 16);
        }
#pragma unroll
        for (int mt = 0; mt < 4; mt++)
#pragma unroll
            for (int nt = 0; nt < 4; nt++)
                mma16h(acc[mt][nt], af[mt][0], af[mt][1], af[mt][2], af[mt][3],
                       bf[nt][0], bf[nt][1]);
    }
}
__device__ __forceinline__ void gemm_h(const __half* __restrict__ Ab, long lda,
        const __half* __restrict__ Bb, long ldb,
        const __half* Ah, const __half* Bh, unsigned as_u32, unsigned bs_u32,
        float acc[4][4][4], int tid, int wm, int wn, int gq, int tg){
    cpAh(Ab, lda, 0, tid, as_u32);
    cpBh(Bb, ldb, 0, tid, bs_u32);
    CP_COMMIT;
    CP_WAIT0;
    __syncthreads();
#pragma unroll
    for (int kt = 0; kt < 8; kt++){
        int cur = kt & 1, nxt = cur ^ 1;
        if (kt < 7){
            cpAh(Ab, lda, kt + 1, tid, as_u32 + (unsigned)(nxt * AH_HALF * 2));
            cpBh(Bb, ldb, kt + 1, tid, bs_u32 + (unsigned)(nxt * BH_HALF * 2));
            CP_COMMIT;
        }
        compute_tile_h(Ah + cur * AH_HALF, Bh + cur * BH_HALF, acc, wm, wn, gq, tg);
        if (kt < 7) CP_WAIT0;
        __syncthreads();
    }
}

// ---------------- K9: out = gelu(msimh@vdh + pb + mbias)*bn + relu(scwh@xh + scb) ------
__global__ void __launch_bounds__(256)
k_fused(const __half* __restrict__ msimh, const __half* __restrict__ vdh,
        const __half* __restrict__ scwh, const __half* __restrict__ xh,
        float* __restrict__ Cg,
        const float* __restrict__ pb, const float* __restrict__ gam,
        const float* __restrict__ bet, const float* __restrict__ scb,
        const float* __restrict__ mbias){
    extern __shared__ __half smh[];
    __half* Ah = smh;                        // 2*AH_HALF
    __half* Bh = smh + 2 * AH_HALF;          // 2*BH_HALF
    unsigned as_u32 = (unsigned)__cvta_generic_to_shared(Ah);
    unsigned bs_u32 = (unsigned)__cvta_generic_to_shared(Bh);
    int tid = threadIdx.x;
    int b = blockIdx.z;
    int h = blockIdx.x >> 5;
    int bz = b * NHH + h;
    const __half* A1 = msimh + (long)bz * 65536 + (long)blockIdx.y * 128 * 256;
    const __half* B1 = vdh + (long)b * NC * HWSZ + blockIdx.x * 128;
    float* C = Cg + (long)b * NC * HWSZ;

    int lane = tid & 31;
    int w = tid >> 5, wm = w & 1, wn = w >> 1;
    int gq = lane >> 2, tg = lane & 3;

    float acc[4][4][4];
#pragma unroll
    for (int mt = 0; mt < 4; mt++)
#pragma unroll
        for (int nt = 0; nt < 4; nt++)
#pragma unroll
            for (int q = 0; q < 4; q++) acc[mt][nt][q] = 0.f;

    gemm_h(A1, 256, B1, HWSZ, Ah, Bh, as_u32, bs_u32, acc, tid, wm, wn, gq, tg);

    int m0 = blockIdx.y * 128 + wm * 64;
    long n0 = (long)blockIdx.x * 128 + wn * 32;

    const float BNS = 0.9999950000374998f;   // 1/sqrt(1+1e-5)
    const float ISQ2 = 0.70710678118654752f;
    float res[4][4][4];
#pragma unroll
    for (int mt = 0; mt < 4; mt++){
        int rA = m0 + mt * 16 + gq, rB = rA + 8;
        float pbA = pb[rA] + mbias[bz * 256 + rA];
        float pbB = pb[rB] + mbias[bz * 256 + rB];
        float gaA = gam[rA] * BNS, gaB = gam[rB] * BNS;
        float beA = bet[rA], beB = bet[rB];
#pragma unroll
        for (int nt = 0; nt < 4; nt++){
            float z;
            z = acc[mt][nt][0] + pbA; res[mt][nt][0] = 0.5f*z*(1.f+erff(z*ISQ2))*gaA + beA;
            z = acc[mt][nt][1] + pbA; res[mt][nt][1] = 0.5f*z*(1.f+erff(z*ISQ2))*gaA + beA;
            z = acc[mt][nt][2] + pbB; res[mt][nt][2] = 0.5f*z*(1.f+erff(z*ISQ2))*gaB + beB;
            z = acc[mt][nt][3] + pbB; res[mt][nt][3] = 0.5f*z*(1.f+erff(z*ISQ2))*gaB + beB;
        }
    }
#pragma unroll
    for (int mt = 0; mt < 4; mt++)
#pragma unroll
        for (int nt = 0; nt < 4; nt++)
#pragma unroll
            for (int q = 0; q < 4; q++) acc[mt][nt][q] = 0.f;
    __syncthreads();

    gemm_h(scwh + (long)blockIdx.y * 128 * 256, 256,
           xh + (long)b * NC * HWSZ + blockIdx.x * 128, HWSZ,
           Ah, Bh, as_u32, bs_u32, acc, tid, wm, wn, gq, tg);
#pragma unroll
    for (int mt = 0; mt < 4; mt++){
        int rA = m0 + mt * 16 + gq, rB = rA + 8;
        float sA = scb[rA], sB = scb[rB];
#pragma unroll
        for (int nt = 0; nt < 4; nt++){
            long col = n0 + nt * 8 + tg * 2;
            float2 o0 = make_float2(res[mt][nt][0] + fmaxf(acc[mt][nt][0] + sA, 0.f),
                                    res[mt][nt][1] + fmaxf(acc[mt][nt][1] + sA, 0.f));
            float2 o1 = make_float2(res[mt][nt][2] + fmaxf(acc[mt][nt][2] + sB, 0.f),
                                    res[mt][nt][3] + fmaxf(acc[mt][nt][3] + sB, 0.f));
            *(float2*)&C[(long)rA * HWSZ + col] = o0;
            *(float2*)&C[(long)rB * HWSZ + col] = o1;
        }
    }
}

// ---------------- launch ----------------
extern "C" void kernel_launch(void* const* d_in, const int* in_sizes, int n_in,
                              void* d_out, int out_size){
    const float* x        = (const float*)d_in[0];
    const float* sc_w     = (const float*)d_in[1];
    const float* sc_b     = (const float*)d_in[2];
    const float* q_w      = (const float*)d_in[3];
    const float* q_b      = (const float*)d_in[4];
    const float* k_w      = (const float*)d_in[5];
    const float* k_b      = (const float*)d_in[6];
    const float* v_dw_w   = (const float*)d_in[7];
    const float* v_dw_b   = (const float*)d_in[8];
    const float* v_pw_w   = (const float*)d_in[9];
    const float* v_pw_b   = (const float*)d_in[10];
    const float* logit_sc = (const float*)d_in[11];
    const float* cpb_w1   = (const float*)d_in[12];
    const float* cpb_b1   = (const float*)d_in[13];
    const float* cpb_w2   = (const float*)d_in[14];
    const float* proj_w   = (const float*)d_in[15];
    const float* proj_b   = (const float*)d_in[16];
    const float* bn_gamma = (const float*)d_in[17];
    const float* bn_beta  = (const float*)d_in[18];
    float* out = (float*)d_out;

    float *xp, *qb, *kb, *sim, *msim, *biasb, *invq, *invk, *mbias;
    __half *vh, *xh, *msimh, *scwh;
    cudaGetSymbolAddress((void**)&xp,   g_xp);
    cudaGetSymbolAddress((void**)&qb,   g_q);
    cudaGetSymbolAddress((void**)&kb,   g_k);
    cudaGetSymbolAddress((void**)&vh,   g_vh);
    cudaGetSymbolAddress((void**)&xh,   g_xh);
    cudaGetSymbolAddress((void**)&sim,  g_sim);
    cudaGetSymbolAddress((void**)&msim, g_msim);
    cudaGetSymbolAddress((void**)&msimh,g_msimh);
    cudaGetSymbolAddress((void**)&scwh, g_scwh);
    cudaGetSymbolAddress((void**)&biasb,g_bias);
    cudaGetSymbolAddress((void**)&invq, g_invq);
    cudaGetSymbolAddress((void**)&invk, g_invk);
    cudaGetSymbolAddress((void**)&mbias,g_mbias);

    const int dw_smem    = 128 * 129 * 4;                          // 66048
    const int mma_smem   = 2 * (A_WORDS + B_WORDS) * 4;            // 71680
    const int sim_smem   = 4 * A_WORDS * 4;                        // 73728
    const int fus_smem   = 2 * (AH_HALF + BH_HALF) * 2;            // 37888
    cudaFuncSetAttribute(k_dw,      cudaFuncAttributeMaxDynamicSharedMemorySize, dw_smem);
    cudaFuncSetAttribute(k_projsim, cudaFuncAttributeMaxDynamicSharedMemorySize, mma_smem);
    cudaFuncSetAttribute(k_simmma,  cudaFuncAttributeMaxDynamicSharedMemorySize, sim_smem);
    cudaFuncSetAttribute(k_fused,   cudaFuncAttributeMaxDynamicSharedMemorySize, fus_smem);

    // 1. maxpool 4x4 (+ x -> half)
    k_maxpool<<<(NB*NC*LP)/256, 256>>>(x, xp, xh);
    // 2/3. q,k grouped pw on pooled
    k_grouped_pw<<<dim3(LP/128, NG, NB), 128>>>(xp, q_w, q_b, qb, LP);
    k_grouped_pw<<<dim3(LP/128, NG, NB), 128>>>(xp, k_w, k_b, kb, LP);
    // 4. depthwise 3x3 + relu: x -> vdh  [profiled slot]
    k_dw<<<dim3(NC, NB), 256, dw_smem>>>(x, v_dw_w, v_dw_b, vh);
    // 5. inverse row norms
    k_rownorm<<<2048, 256>>>(qb, kb, invq, invk);
    // 6. sc_w -> half
    k_whalf<<<256, 256>>>(sc_w, scwh);
    // 7. CPB bias table
    k_cpb<<<256, 256>>>(cpb_w1, cpb_b1, cpb_w2, biasb);
    // 8. sim GEMM (tf32 mma) + scale + bias
    k_simmma<<<dim3(2, 2, NB*NHH), 256, sim_smem>>>(qb, kb, invq, invk, logit_sc, biasb, sim);
    // 9. double softmax (warp per row)
    k_dsoftmax<<<1024, 256>>>(sim);
    // 10. msim = proj @ sim per (b,h)
    k_projsim<<<dim3(2, 2, NB*NHH), 256, mma_smem>>>(proj_w, sim, msim);
    // 11. fold pw conv into msim -> half + mbias
    k_fold<<<NB*NHH, 256>>>(msim, v_pw_w, v_pw_b, msimh, mbias);
    // 12. out = gelu(msimh@vdh + pb + mbias)*bn + relu(scwh@xh + scb)  (fp16 HMMA)
    k_fused<<<dim3(HWSZ/128, 2, NB), 256, fus_smem>>>(msimh, vh, scwh, xh, out,
                                                      proj_b, bn_gamma, bn_beta, sc_b, mbias);
}

// round 17
// speedup vs baseline: 1.2176x; 1.0305x over previous
#include <cuda_runtime.h>
#include <cuda_fp16.h>
#include <math.h>

// ---------------- problem constants ----------------
#define NB   8
#define NC   256
#define NG   4
#define CG   64
#define NHH  4
#define WW   128
#define HWSZ 16384        // 128*128
#define LP   1024         // pooled spatial (32*32)
#define DH   256          // LP/NH
#define DV   4096         // HW/NH

// ---------------- scratch ----------------
__device__ float  g_xp [NB*NC*LP];
__device__ float  g_q  [NB*NC*LP];
__device__ float  g_k  [NB*NC*LP];
__device__ __half g_vh [NB*NC*HWSZ];         // dw output (half)
__device__ __half g_xh [NB*NC*HWSZ];         // x converted to half
__device__ float  g_sim[NB*NHH*256*256];
__device__ float  g_msim[NB*NHH*256*256];
__device__ __half g_msimh[NB*NHH*256*256];   // folded msim (half)
__device__ __half g_scwh[256*256];           // sc_w (half)
__device__ float  g_bias[NHH*256*256];
__device__ float  g_invq[NB*NHH*256];
__device__ float  g_invk[NB*NHH*256];
__device__ float  g_mbias[NB*NHH*256];

// ---------------- helpers ----------------
__device__ __forceinline__ float warpRedSum(float v){
#pragma unroll
    for (int o = 16; o > 0; o >>= 1) v += __shfl_xor_sync(0xffffffffu, v, o);
    return v;
}
__device__ __forceinline__ float warpRedMax(float v){
#pragma unroll
    for (int o = 16; o > 0; o >>= 1) v = fmaxf(v, __shfl_xor_sync(0xffffffffu, v, o));
    return v;
}
__device__ __forceinline__ float warpRedMin(float v){
#pragma unroll
    for (int o = 16; o > 0; o >>= 1) v = fminf(v, __shfl_xor_sync(0xffffffffu, v, o));
    return v;
}
__device__ __forceinline__ unsigned f2tf(float f){
    unsigned u; asm("cvt.rna.tf32.f32 %0, %1;" : "=r"(u) : "f"(f)); return u;
}
__device__ __forceinline__ void mma8(float* c, unsigned a0, unsigned a1, unsigned a2, unsigned a3,
                                     unsigned b0, unsigned b1){
    asm volatile("mma.sync.aligned.m16n8k8.row.col.f32.tf32.tf32.f32 "
                 "{%0,%1,%2,%3},{%4,%5,%6,%7},{%8,%9},{%0,%1,%2,%3};"
                 : "+f"(c[0]), "+f"(c[1]), "+f"(c[2]), "+f"(c[3])
                 : "r"(a0), "r"(a1), "r"(a2), "r"(a3), "r"(b0), "r"(b1));
}
__device__ __forceinline__ void mma16h(float* c, unsigned a0, unsigned a1, unsigned a2, unsigned a3,
                                       unsigned b0, unsigned b1){
    asm volatile("mma.sync.aligned.m16n8k16.row.col.f32.f16.f16.f32 "
                 "{%0,%1,%2,%3},{%4,%5,%6,%7},{%8,%9},{%0,%1,%2,%3};"
                 : "+f"(c[0]), "+f"(c[1]), "+f"(c[2]), "+f"(c[3])
                 : "r"(a0), "r"(a1), "r"(a2), "r"(a3), "r"(b0), "r"(b1));
}
__device__ __forceinline__ void ldsm4(unsigned &r0, unsigned &r1, unsigned &r2, unsigned &r3,
                                      unsigned addr){
    asm volatile("ldmatrix.sync.aligned.m8n8.x4.shared.b16 {%0,%1,%2,%3}, [%4];"
                 : "=r"(r0), "=r"(r1), "=r"(r2), "=r"(r3) : "r"(addr));
}
__device__ __forceinline__ void ldsm4t(unsigned &r0, unsigned &r1, unsigned &r2, unsigned &r3,
                                       unsigned addr){
    asm volatile("ldmatrix.sync.aligned.m8n8.x4.trans.shared.b16 {%0,%1,%2,%3}, [%4];"
                 : "=r"(r0), "=r"(r1), "=r"(r2), "=r"(r3) : "r"(addr));
}
#define CP_ASYNC16(saddr, gptr) \
    asm volatile("cp.async.cg.shared.global [%0], [%1], 16;" :: "r"(saddr), "l"(gptr))
#define CP_COMMIT  asm volatile("cp.async.commit_group;")
#define CP_WAIT0   asm volatile("cp.async.wait_group 0;")

// ---------------- K1: 4x4 maxpool + x->half conversion ----------------
__global__ void k_maxpool(const float* __restrict__ xin, float* __restrict__ out,
                          __half* __restrict__ xh){
    int idx = blockIdx.x * 256 + threadIdx.x;
    int pp = idx & 1023;
    int bc = idx >> 10;
    int ph = pp >> 5, pw = pp & 31;
    const float* xp = xin + (long)bc * HWSZ + (ph * 4) * WW + pw * 4;
    __half* xhp = xh + (long)bc * HWSZ + (ph * 4) * WW + pw * 4;
    float m = -3.4e38f;
#pragma unroll
    for (int i = 0; i < 4; i++){
        float4 v4 = *(const float4*)(xp + i * WW);
        m = fmaxf(m, fmaxf(fmaxf(v4.x, v4.y), fmaxf(v4.z, v4.w)));
        __half2 h0 = __floats2half2_rn(v4.x, v4.y);
        __half2 h1 = __floats2half2_rn(v4.z, v4.w);
        *(__half2*)(xhp + i * WW)     = h0;
        *(__half2*)(xhp + i * WW + 2) = h1;
    }
    out[idx] = m;
}

// ---------------- K2: grouped 1x1 pw conv (pooled q/k path) ----------------
__global__ void k_grouped_pw(const float* __restrict__ in, const float* __restrict__ w,
                             const float* __restrict__ bias, float* __restrict__ out, int L){
    __shared__ float wsT[64 * 64];
    __shared__ float xs[64][128];
    int g = blockIdx.y, b = blockIdx.z;
    int l0 = blockIdx.x * 128;
    int t = threadIdx.x;
    for (int idx = t; idx < 4096; idx += 128){
        int i = idx >> 6, j = idx & 63;
        wsT[j * 64 + i] = w[g * 4096 + idx];
    }
    const float* ip = in + ((long)(b * NC + g * CG)) * L + l0;
#pragma unroll 8
    for (int j = 0; j < 64; j++) xs[j][t] = ip[(long)j * L + t];
    __syncthreads();
    float acc[64];
#pragma unroll
    for (int i = 0; i < 64; i++) acc[i] = 0.f;
#pragma unroll 4
    for (int j = 0; j < 64; j++){
        float xv = xs[j][t];
        const float4* wr = (const float4*)(wsT + j * 64);
#pragma unroll
        for (int i4 = 0; i4 < 16; i4++){
            float4 wv = wr[i4];
            acc[i4*4+0] += wv.x * xv;
            acc[i4*4+1] += wv.y * xv;
            acc[i4*4+2] += wv.z * xv;
            acc[i4*4+3] += wv.w * xv;
        }
    }
    float* op = out + ((long)(b * NC + g * CG)) * L + l0;
#pragma unroll 8
    for (int i = 0; i < 64; i++)
        op[(long)i * L + t] = acc[i] + bias[g * CG + i];
}

// ---------------- K3: depthwise 3x3 + relu (reads xh half) -> half ----------------
__global__ void __launch_bounds__(256)
k_dw(const __half* __restrict__ xhin, const float* __restrict__ dw_w,
     const float* __restrict__ dw_b, __half* __restrict__ vd){
    extern __shared__ float xs[];          // 128*129 floats
    int c = blockIdx.x, b = blockIdx.y;
    const __half* xp = xhin + ((long)(b * NC + c)) * HWSZ;
    int t = threadIdx.x;

#pragma unroll
    for (int i = 0; i < 8; i++){
        int vid = t + i * 256;             // 8-half chunk id, 2048 total
        int row = vid >> 4, col8 = (vid & 15) * 8;
        uint4 raw = *(const uint4*)(xp + row * 128 + col8);
        const __half2* h2 = (const __half2*)&raw;
        float* d = &xs[row * 129 + col8];
        float2 f0 = __half22float2(h2[0]);
        float2 f1 = __half22float2(h2[1]);
        float2 f2 = __half22float2(h2[2]);
        float2 f3 = __half22float2(h2[3]);
        d[0] = f0.x; d[1] = f0.y; d[2] = f1.x; d[3] = f1.y;
        d[4] = f2.x; d[5] = f2.y; d[6] = f3.x; d[7] = f3.y;
    }
    float wv[9];
#pragma unroll
    for (int i = 0; i < 9; i++) wv[i] = dw_w[c * 9 + i];
    float bias = dw_b[c];
    __syncthreads();

    int y = t & 127, half = t >> 7;
    int x0 = half * 64;
    float fm = (y > 0)   ? 1.f : 0.f;
    float fp = (y < 127) ? 1.f : 0.f;
    const float* rm = &xs[(y > 0 ? y - 1 : 0) * 129];
    const float* rc = &xs[y * 129];
    const float* rp = &xs[(y < 127 ? y + 1 : 127) * 129];
    float w00 = wv[0]*fm, w01 = wv[1]*fm, w02 = wv[2]*fm;
    float w10 = wv[3],    w11 = wv[4],    w12 = wv[5];
    float w20 = wv[6]*fp, w21 = wv[7]*fp, w22 = wv[8]*fp;

    float pm, pc, pp, cm, cc, cp;
    if (x0 > 0){ pm = rm[x0 - 1]; pc = rc[x0 - 1]; pp = rp[x0 - 1]; }
    else       { pm = 0.f; pc = 0.f; pp = 0.f; }
    cm = rm[x0]; cc = rc[x0]; cp = rp[x0];

    __half* orow = vd + ((long)(b * NC + c)) * HWSZ + y * 128 + x0;
    __align__(16) __half ob[8];
#pragma unroll
    for (int xi = 0; xi < 64; xi++){
        int xn = x0 + xi + 1;
        float nm, nc, np;
        if (xn < 128){ nm = rm[xn]; nc = rc[xn]; np = rp[xn]; }
        else         { nm = 0.f; nc = 0.f; np = 0.f; }
        float s = bias;
        s += w00 * pm + w01 * cm + w02 * nm;
        s += w10 * pc + w11 * cc + w12 * nc;
        s += w20 * pp + w21 * cp + w22 * np;
        ob[xi & 7] = __float2half(fmaxf(s, 0.f));
        if ((xi & 7) == 7)
            *(uint4*)&orow[xi - 7] = *(const uint4*)ob;
        pm = cm; pc = cc; pp = cp;
        cm = nm; cc = nc; cp = np;
    }
}

// ---------------- K4: row inverse norms of q,k heads ----------------
__global__ void k_rownorm(const float* __restrict__ q, const float* __restrict__ k,
                          float* __restrict__ invq, float* __restrict__ invk){
    int gw = (blockIdx.x * blockDim.x + threadIdx.x) >> 5;
    int lane = threadIdx.x & 31;
    int sel = gw >> 13;
    int r = gw & 8191;
    int b = r >> 10; int rem = r & 1023; int h = rem >> 8; int c = rem & 255;
    const float* src = (sel ? k : q) + (long)b * NC * LP + (long)c * LP + h * DH;
    float s = 0.f;
#pragma unroll
    for (int d = lane; d < DH; d += 32){ float v = src[d]; s += v * v; }
    s = warpRedSum(s);
    if (lane == 0){
        float inv = 1.f / fmaxf(sqrtf(s), 1e-12f);
        (sel ? invk : invq)[(b * NHH + h) * 256 + c] = inv;
    }
}

// ---------------- K4b: sc_w -> half ----------------
__global__ void k_whalf(const float* __restrict__ w, __half* __restrict__ wh){
    int i = blockIdx.x * 256 + threadIdx.x;
    wh[i] = __float2half(w[i]);
}

// ---------------- K5: CPB relative position bias ----------------
__global__ void k_cpb(const float* __restrict__ w1, const float* __restrict__ b1,
                      const float* __restrict__ w2, float* __restrict__ biasb){
    __shared__ float s1[64], sb1[64], s2[256];
    int t = threadIdx.x;
    if (t < 64){ s1[t] = w1[t]; sb1[t] = b1[t]; }
    s2[t] = w2[t];
    __syncthreads();
    int idx = blockIdx.x * 256 + t;
    int i = idx >> 8, j = idx & 255;
    float coords = (float)(j - i);
    float rel = coords * (8.0f / 255.0f);
    float sg = (rel > 0.f) ? 1.f : ((rel < 0.f) ? -1.f : 0.f);
    float f = sg * log2f(fabsf(rel) + 1.f) * (1.f / 3.f);
    float o0 = 0.f, o1 = 0.f, o2 = 0.f, o3 = 0.f;
#pragma unroll 8
    for (int h = 0; h < 64; h++){
        float hv = fmaxf(f * s1[h] + sb1[h], 0.f);
        o0 += hv * s2[h * 4 + 0];
        o1 += hv * s2[h * 4 + 1];
        o2 += hv * s2[h * 4 + 2];
        o3 += hv * s2[h * 4 + 3];
    }
    biasb[0 * 65536 + idx] = 1.f / (1.f + expf(-o0));
    biasb[1 * 65536 + idx] = 1.f / (1.f + expf(-o1));
    biasb[2 * 65536 + idx] = 1.f / (1.f + expf(-o2));
    biasb[3 * 65536 + idx] = 1.f / (1.f + expf(-o3));
}

// ---------------- K7: double softmax, warp per row ----------------
__global__ void k_dsoftmax(float* __restrict__ simb){
    int row = blockIdx.x * 8 + (threadIdx.x >> 5);
    int lane = threadIdx.x & 31;
    float* p = simb + (long)row * 256;
    float v[8];
#pragma unroll
    for (int j = 0; j < 8; j++) v[j] = p[lane + 32 * j];
    float m = v[0];
#pragma unroll
    for (int j = 1; j < 8; j++) m = fmaxf(m, v[j]);
    m = warpRedMax(m);
    float s = 0.f;
#pragma unroll
    for (int j = 0; j < 8; j++){ v[j] = expf(v[j] - m); s += v[j]; }
    s = warpRedSum(s);
    float inv = 1.f / s;
    float mn = v[0];
#pragma unroll
    for (int j = 1; j < 8; j++) mn = fminf(mn, v[j]);
    mn = warpRedMin(mn);
    float e2[8]; float s2 = 0.f;
#pragma unroll
    for (int j = 0; j < 8; j++){ e2[j] = expf((mn - v[j]) * inv); s2 += e2[j]; }
    s2 = warpRedSum(s2);
    float i2 = 1.f / s2;
#pragma unroll
    for (int j = 0; j < 8; j++) p[lane + 32 * j] = e2[j] * i2;
}

// ---------------- tf32 tile helpers (simmma / projsim) ----------------
#define A_WORDS 4608   // 128*36
#define B_WORDS 4352   // 32*136

__device__ __forceinline__ void ldA(const float* __restrict__ Ab, long lda, int kt, int tid, float4* ar){
#pragma unroll
    for (int i = 0; i < 4; i++){
        int vid = tid + i * 256;
        int r = vid >> 3, c4 = (vid & 7) << 2;
        ar[i] = *(const float4*)(Ab + (long)r * lda + kt * 32 + c4);
    }
}
__device__ __forceinline__ void stA(unsigned* As, int tid, const float4* ar){
#pragma unroll
    for (int i = 0; i < 4; i++){
        int vid = tid + i * 256;
        int r = vid >> 3, c4 = (vid & 7) << 2;
        uint4 ua; ua.x = f2tf(ar[i].x); ua.y = f2tf(ar[i].y); ua.z = f2tf(ar[i].z); ua.w = f2tf(ar[i].w);
        *(uint4*)&As[r * 36 + c4] = ua;
    }
}
__device__ __forceinline__ void ldB(const float* __restrict__ Bb, long ldb, int kt, int tid, float4* br){
#pragma unroll
    for (int i = 0; i < 4; i++){
        int vid = tid + i * 256;
        int kr = vid >> 5, n4 = (vid & 31) << 2;
        br[i] = *(const float4*)(Bb + (long)(kt * 32 + kr) * ldb + n4);
    }
}
__device__ __forceinline__ void stB(unsigned* Bs, int tid, const float4* br){
#pragma unroll
    for (int i = 0; i < 4; i++){
        int vid = tid + i * 256;
        int kr = vid >> 5, n4 = (vid & 31) << 2;
        uint4 ub; ub.x = f2tf(br[i].x); ub.y = f2tf(br[i].y); ub.z = f2tf(br[i].z); ub.w = f2tf(br[i].w);
        *(uint4*)&Bs[kr * 136 + n4] = ub;
    }
}
__device__ __forceinline__ void compute_tile(const unsigned* As, const unsigned* Bs,
        float acc[4][4][4], int wm, int wn, int gq, int tg){
#pragma unroll
    for (int ks = 0; ks < 4; ks++){
        unsigned af[4][4], bf[4][2];
        int c = ks * 8 + tg;
#pragma unroll
        for (int mt = 0; mt < 4; mt++){
            int r = wm * 64 + mt * 16 + gq;
            af[mt][0] = As[r * 36 + c];
            af[mt][1] = As[(r + 8) * 36 + c];
            af[mt][2] = As[r * 36 + c + 4];
            af[mt][3] = As[(r + 8) * 36 + c + 4];
        }
#pragma unroll
        for (int nt = 0; nt < 4; nt++){
            int cc = wn * 32 + nt * 8 + gq;
            bf[nt][0] = Bs[c * 136 + cc];
            bf[nt][1] = Bs[(c + 4) * 136 + cc];
        }
#pragma unroll
        for (int mt = 0; mt < 4; mt++)
#pragma unroll
            for (int nt = 0; nt < 4; nt++)
                mma8(acc[mt][nt], af[mt][0], af[mt][1], af[mt][2], af[mt][3],
                     bf[nt][0], bf[nt][1]);
    }
}
__device__ __forceinline__ void gemm_db(const float* __restrict__ Ab,
        const float* __restrict__ Bb, long ldb,
        unsigned* As, unsigned* Bs, float acc[4][4][4], int tid){
    int lane = tid & 31, w = tid >> 5, wm = w & 1, wn = w >> 1;
    int gq = lane >> 2, tg = lane & 3;
    float4 ar[4], br[4];
    ldA(Ab, 256, 0, tid, ar); ldB(Bb, ldb, 0, tid, br);
    stA(As, tid, ar); stB(Bs, tid, br);
    __syncthreads();
#pragma unroll
    for (int kt = 0; kt < 8; kt++){
        int cur = kt & 1;
        if (kt < 7){ ldA(Ab, 256, kt + 1, tid, ar); ldB(Bb, ldb, kt + 1, tid, br); }
        compute_tile(As + cur * A_WORDS, Bs + cur * B_WORDS, acc, wm, wn, gq, tg);
        if (kt < 7){ stA(As + (cur ^ 1) * A_WORDS, tid, ar); stB(Bs + (cur ^ 1) * B_WORDS, tid, br); }
        __syncthreads();
    }
}

// ---------------- K6: sim via tf32 MMA ----------------
__global__ void __launch_bounds__(256)
k_simmma(const float* __restrict__ qb, const float* __restrict__ kb,
         const float* __restrict__ invq, const float* __restrict__ invk,
         const float* __restrict__ ls, const float* __restrict__ biasb,
         float* __restrict__ simb){
    extern __shared__ unsigned smu[];
    unsigned* As  = smu;
    unsigned* BsT = smu + 2 * A_WORDS;
    int tid = threadIdx.x;
    int bz = blockIdx.z;
    int b = bz >> 2, h = bz & 3;
    const float* qbase = qb + (long)b * NC * LP + h * DH + (long)blockIdx.y * 128 * LP;
    const float* kbase = kb + (long)b * NC * LP + h * DH + (long)blockIdx.x * 128 * LP;

    int lane = tid & 31, w = tid >> 5, wm = w & 1, wn = w >> 1;
    int gq = lane >> 2, tg = lane & 3;

    float acc[4][4][4];
#pragma unroll
    for (int mt = 0; mt < 4; mt++)
#pragma unroll
        for (int nt = 0; nt < 4; nt++)
#pragma unroll
            for (int q = 0; q < 4; q++) acc[mt][nt][q] = 0.f;

    float4 ar[4], br[4];
    ldA(qbase, LP, 0, tid, ar); ldA(kbase, LP, 0, tid, br);
    stA(As, tid, ar); stA(BsT, tid, br);
    __syncthreads();
#pragma unroll
    for (int kt = 0; kt < 8; kt++){
        int cur = kt & 1;
        if (kt < 7){ ldA(qbase, LP, kt + 1, tid, ar); ldA(kbase, LP, kt + 1, tid, br); }
        {
            const unsigned* Ac = As + cur * A_WORDS;
            const unsigned* Bc = BsT + cur * A_WORDS;
#pragma unroll
            for (int ks = 0; ks < 4; ks++){
                unsigned af[4][4], bf[4][2];
                int c = ks * 8 + tg;
#pragma unroll
                for (int mt = 0; mt < 4; mt++){
                    int r = wm * 64 + mt * 16 + gq;
                    af[mt][0] = Ac[r * 36 + c];
                    af[mt][1] = Ac[(r + 8) * 36 + c];
                    af[mt][2] = Ac[r * 36 + c + 4];
                    af[mt][3] = Ac[(r + 8) * 36 + c + 4];
                }
#pragma unroll
                for (int nt = 0; nt < 4; nt++){
                    int cc = wn * 32 + nt * 8 + gq;
                    bf[nt][0] = Bc[cc * 36 + c];
                    bf[nt][1] = Bc[cc * 36 + c + 4];
                }
#pragma unroll
                for (int mt = 0; mt < 4; mt++)
#pragma unroll
                    for (int nt = 0; nt < 4; nt++)
                        mma8(acc[mt][nt], af[mt][0], af[mt][1], af[mt][2], af[mt][3],
                             bf[nt][0], bf[nt][1]);
            }
        }
        if (kt < 7){ stA(As + (cur ^ 1) * A_WORDS, tid, ar); stA(BsT + (cur ^ 1) * A_WORDS, tid, br); }
        __syncthreads();
    }

    float scale = expf(fminf(ls[h], 4.6051702f));
    int c0 = blockIdx.y * 128, e0 = blockIdx.x * 128;
    float* Cp = simb + (long)bz * 65536;
#pragma unroll
    for (int mt = 0; mt < 4; mt++){
        int rA = c0 + wm * 64 + mt * 16 + gq, rB = rA + 8;
        float iqA = invq[bz * 256 + rA] * scale;
        float iqB = invq[bz * 256 + rB] * scale;
#pragma unroll
        for (int nt = 0; nt < 4; nt++){
            int col = e0 + wn * 32 + nt * 8 + tg * 2;
            float ik0 = invk[bz * 256 + col], ik1 = invk[bz * 256 + col + 1];
            const float* bb = biasb + h * 65536;
            float2 o0 = make_float2(acc[mt][nt][0] * iqA * ik0 + bb[rA * 256 + col],
                                    acc[mt][nt][1] * iqA * ik1 + bb[rA * 256 + col + 1]);
            float2 o1 = make_float2(acc[mt][nt][2] * iqB * ik0 + bb[rB * 256 + col],
                                    acc[mt][nt][3] * iqB * ik1 + bb[rB * 256 + col + 1]);
            *(float2*)&Cp[(long)rA * 256 + col] = o0;
            *(float2*)&Cp[(long)rB * 256 + col] = o1;
        }
    }
}

// ---------------- K8: msim = proj @ sim  per (b,h) ----------------
__global__ void __launch_bounds__(256)
k_projsim(const float* __restrict__ proj, const float* __restrict__ simb,
          float* __restrict__ msim){
    extern __shared__ unsigned smu[];
    unsigned* As = smu;
    unsigned* Bs = smu + 2 * A_WORDS;
    int tid = threadIdx.x;
    int bz = blockIdx.z;
    const float* Ab = proj + (long)blockIdx.y * 128 * 256;
    const float* Bb = simb + (long)bz * 65536 + blockIdx.x * 128;
    float* C = msim + (long)bz * 65536;

    float acc[4][4][4];
#pragma unroll
    for (int mt = 0; mt < 4; mt++)
#pragma unroll
        for (int nt = 0; nt < 4; nt++)
#pragma unroll
            for (int q = 0; q < 4; q++) acc[mt][nt][q] = 0.f;

    gemm_db(Ab, Bb, 256, As, Bs, acc, tid);

    int lane = tid & 31;
    int w = tid >> 5, wm = w & 1, wn = w >> 1;
    int gq = lane >> 2, tg = lane & 3;
    int m0 = blockIdx.y * 128 + wm * 64;
    int n0 = blockIdx.x * 128 + wn * 32;
#pragma unroll
    for (int mt = 0; mt < 4; mt++){
        int rA = m0 + mt * 16 + gq;
#pragma unroll
        for (int nt = 0; nt < 4; nt++){
            int col = n0 + nt * 8 + tg * 2;
            *(float2*)&C[(long)rA * 256 + col]       = make_float2(acc[mt][nt][0], acc[mt][nt][1]);
            *(float2*)&C[(long)(rA + 8) * 256 + col] = make_float2(acc[mt][nt][2], acc[mt][nt][3]);
        }
    }
}

// ---------------- K8b: fold pw into msim -> half; mbias ----------------
__global__ void __launch_bounds__(256)
k_fold(const float* __restrict__ msim, const float* __restrict__ pw_w,
       const float* __restrict__ pw_b, __half* __restrict__ msimh,
       float* __restrict__ mbias){
    __shared__ float Ws[4096];
    __shared__ float pbs[256];
    int bz = blockIdx.x;
    int t = threadIdx.x;
    pbs[t] = pw_b[t];
    const float* row = msim + (long)bz * 65536 + (long)t * 256;
    __half* rowh = msimh + (long)bz * 65536 + (long)t * 256;
    float mb = 0.f;
    for (int g = 0; g < 4; g++){
        __syncthreads();
        for (int i = t; i < 4096; i += 256) Ws[i] = pw_w[g * 4096 + i];
        __syncthreads();
        float a[64];
#pragma unroll
        for (int j = 0; j < 64; j++) a[j] = row[g * 64 + j];
        float acc[64];
#pragma unroll
        for (int j = 0; j < 64; j++) acc[j] = 0.f;
        for (int eo = 0; eo < 64; eo++){
            float av = a[eo];
            mb += av * pbs[g * 64 + eo];
            const float4* wr = (const float4*)(Ws + eo * 64);
#pragma unroll
            for (int i4 = 0; i4 < 16; i4++){
                float4 wv = wr[i4];
                acc[i4*4+0] += av * wv.x;
                acc[i4*4+1] += av * wv.y;
                acc[i4*4+2] += av * wv.z;
                acc[i4*4+3] += av * wv.w;
            }
        }
#pragma unroll
        for (int j2 = 0; j2 < 32; j2++)
            *(__half2*)&rowh[g * 64 + j2 * 2] = __floats2half2_rn(acc[j2*2], acc[j2*2+1]);
    }
    mbias[bz * 256 + t] = mb;
}

// ---------------- fp16 GEMM core for k_fused (ldmatrix) ----------------
#define AH_PITCH 40           // halves per A row
#define AH_HALF  (128*40)     // 5120 halves/stage
#define BH_PITCH 136          // halves per B row
#define BH_HALF  (32*136)     // 4352 halves/stage

__device__ __forceinline__ void cpAh(const __half* __restrict__ Ab, long lda, int kt, int tid,
                                     unsigned as_u32){
#pragma unroll
    for (int i = 0; i < 2; i++){
        int u = tid + i * 256;
        int r = u >> 2, c8 = (u & 3) * 8;
        CP_ASYNC16(as_u32 + (unsigned)((r * AH_PITCH + c8) * 2),
                   Ab + (long)r * lda + kt * 32 + c8);
    }
}
__device__ __forceinline__ void cpBh(const __half* __restrict__ Bb, long ldb, int kt, int tid,
                                     unsigned bs_u32){
#pragma unroll
    for (int i = 0; i < 2; i++){
        int u = tid + i * 256;
        int kr = u >> 4, n8 = (u & 15) * 8;
        CP_ASYNC16(bs_u32 + (unsigned)((kr * BH_PITCH + n8) * 2),
                   Bb + (long)(kt * 32 + kr) * ldb + n8);
    }
}
__device__ __forceinline__ void compute_tile_h(unsigned ah_u32, unsigned bh_u32,
        float acc[4][4][4], int wm, int wn, int lane){
    int r15 = lane & 15, hi8 = (lane >> 4) * 8;
#pragma unroll
    for (int ks = 0; ks < 2; ks++){
        int k0 = ks * 16;
        unsigned af[4][4], bf[4][2];
#pragma unroll
        for (int mt = 0; mt < 4; mt++){
            int r = wm * 64 + mt * 16 + r15;
            ldsm4(af[mt][0], af[mt][1], af[mt][2], af[mt][3],
                  ah_u32 + (unsigned)((r * AH_PITCH + k0 + hi8) * 2));
        }
        int krow = k0 + r15;
        ldsm4t(bf[0][0], bf[0][1], bf[1][0], bf[1][1],
               bh_u32 + (unsigned)((krow * BH_PITCH + wn * 32 + hi8) * 2));
        ldsm4t(bf[2][0], bf[2][1], bf[3][0], bf[3][1],
               bh_u32 + (unsigned)((krow * BH_PITCH + wn * 32 + 16 + hi8) * 2));
#pragma unroll
        for (int mt = 0; mt < 4; mt++)
#pragma unroll
            for (int nt = 0; nt < 4; nt++)
                mma16h(acc[mt][nt], af[mt][0], af[mt][1], af[mt][2], af[mt][3],
                       bf[nt][0], bf[nt][1]);
    }
}
__device__ __forceinline__ void gemm_h(const __half* __restrict__ Ab, long lda,
        const __half* __restrict__ Bb, long ldb,
        unsigned as_u32, unsigned bs_u32,
        float acc[4][4][4], int tid, int wm, int wn, int lane){
    cpAh(Ab, lda, 0, tid, as_u32);
    cpBh(Bb, ldb, 0, tid, bs_u32);
    CP_COMMIT;
    CP_WAIT0;
    __syncthreads();
#pragma unroll
    for (int kt = 0; kt < 8; kt++){
        int cur = kt & 1, nxt = cur ^ 1;
        if (kt < 7){
            cpAh(Ab, lda, kt + 1, tid, as_u32 + (unsigned)(nxt * AH_HALF * 2));
            cpBh(Bb, ldb, kt + 1, tid, bs_u32 + (unsigned)(nxt * BH_HALF * 2));
            CP_COMMIT;
        }
        compute_tile_h(as_u32 + (unsigned)(cur * AH_HALF * 2),
                       bs_u32 + (unsigned)(cur * BH_HALF * 2), acc, wm, wn, lane);
        if (kt < 7) CP_WAIT0;
        __syncthreads();
    }
}

// ---------------- K9: out = gelu(msimh@vdh + pb + mbias)*bn + relu(scwh@xh + scb) ------
__global__ void __launch_bounds__(256)
k_fused(const __half* __restrict__ msimh, const __half* __restrict__ vdh,
        const __half* __restrict__ scwh, const __half* __restrict__ xh,
        float* __restrict__ Cg,
        const float* __restrict__ pb, const float* __restrict__ gam,
        const float* __restrict__ bet, const float* __restrict__ scb,
        const float* __restrict__ mbias){
    extern __shared__ __half smh[];
    __half* Ah = smh;                        // 2*AH_HALF
    __half* Bh = smh + 2 * AH_HALF;          // 2*BH_HALF
    unsigned as_u32 = (unsigned)__cvta_generic_to_shared(Ah);
    unsigned bs_u32 = (unsigned)__cvta_generic_to_shared(Bh);
    int tid = threadIdx.x;
    int b = blockIdx.z;
    int h = blockIdx.x >> 5;
    int bz = b * NHH + h;
    const __half* A1 = msimh + (long)bz * 65536 + (long)blockIdx.y * 128 * 256;
    const __half* B1 = vdh + (long)b * NC * HWSZ + blockIdx.x * 128;
    float* C = Cg + (long)b * NC * HWSZ;

    int lane = tid & 31;
    int w = tid >> 5, wm = w & 1, wn = w >> 1;
    int gq = lane >> 2, tg = lane & 3;

    float acc[4][4][4];
#pragma unroll
    for (int mt = 0; mt < 4; mt++)
#pragma unroll
        for (int nt = 0; nt < 4; nt++)
#pragma unroll
            for (int q = 0; q < 4; q++) acc[mt][nt][q] = 0.f;

    gemm_h(A1, 256, B1, HWSZ, as_u32, bs_u32, acc, tid, wm, wn, lane);

    int m0 = blockIdx.y * 128 + wm * 64;
    long n0 = (long)blockIdx.x * 128 + wn * 32;

    const float BNS = 0.9999950000374998f;   // 1/sqrt(1+1e-5)
    const float ISQ2 = 0.70710678118654752f;
    float res[4][4][4];
#pragma unroll
    for (int mt = 0; mt < 4; mt++){
        int rA = m0 + mt * 16 + gq, rB = rA + 8;
        float pbA = pb[rA] + mbias[bz * 256 + rA];
        float pbB = pb[rB] + mbias[bz * 256 + rB];
        float gaA = gam[rA] * BNS, gaB = gam[rB] * BNS;
        float beA = bet[rA], beB = bet[rB];
#pragma unroll
        for (int nt = 0; nt < 4; nt++){
            float z;
            z = acc[mt][nt][0] + pbA; res[mt][nt][0] = 0.5f*z*(1.f+erff(z*ISQ2))*gaA + beA;
            z = acc[mt][nt][1] + pbA; res[mt][nt][1] = 0.5f*z*(1.f+erff(z*ISQ2))*gaA + beA;
            z = acc[mt][nt][2] + pbB; res[mt][nt][2] = 0.5f*z*(1.f+erff(z*ISQ2))*gaB + beB;
            z = acc[mt][nt][3] + pbB; res[mt][nt][3] = 0.5f*z*(1.f+erff(z*ISQ2))*gaB + beB;
        }
    }
#pragma unroll
    for (int mt = 0; mt < 4; mt++)
#pragma unroll
        for (int nt = 0; nt < 4; nt++)
#pragma unroll
            for (int q = 0; q < 4; q++) acc[mt][nt][q] = 0.f;
    __syncthreads();

    gemm_h(scwh + (long)blockIdx.y * 128 * 256, 256,
           xh + (long)b * NC * HWSZ + blockIdx.x * 128, HWSZ,
           as_u32, bs_u32, acc, tid, wm, wn, lane);
#pragma unroll
    for (int mt = 0; mt < 4; mt++){
        int rA = m0 + mt * 16 + gq, rB = rA + 8;
        float sA = scb[rA], sB = scb[rB];
#pragma unroll
        for (int nt = 0; nt < 4; nt++){
            long col = n0 + nt * 8 + tg * 2;
            float2 o0 = make_float2(res[mt][nt][0] + fmaxf(acc[mt][nt][0] + sA, 0.f),
                                    res[mt][nt][1] + fmaxf(acc[mt][nt][1] + sA, 0.f));
            float2 o1 = make_float2(res[mt][nt][2] + fmaxf(acc[mt][nt][2] + sB, 0.f),
                                    res[mt][nt][3] + fmaxf(acc[mt][nt][3] + sB, 0.f));
            *(float2*)&C[(long)rA * HWSZ + col] = o0;
            *(float2*)&C[(long)rB * HWSZ + col] = o1;
        }
    }
}

// ---------------- launch ----------------
extern "C" void kernel_launch(void* const* d_in, const int* in_sizes, int n_in,
                              void* d_out, int out_size){
    const float* x        = (const float*)d_in[0];
    const float* sc_w     = (const float*)d_in[1];
    const float* sc_b     = (const float*)d_in[2];
    const float* q_w      = (const float*)d_in[3];
    const float* q_b      = (const float*)d_in[4];
    const float* k_w      = (const float*)d_in[5];
    const float* k_b      = (const float*)d_in[6];
    const float* v_dw_w   = (const float*)d_in[7];
    const float* v_dw_b   = (const float*)d_in[8];
    const float* v_pw_w   = (const float*)d_in[9];
    const float* v_pw_b   = (const float*)d_in[10];
    const float* logit_sc = (const float*)d_in[11];
    const float* cpb_w1   = (const float*)d_in[12];
    const float* cpb_b1   = (const float*)d_in[13];
    const float* cpb_w2   = (const float*)d_in[14];
    const float* proj_w   = (const float*)d_in[15];
    const float* proj_b   = (const float*)d_in[16];
    const float* bn_gamma = (const float*)d_in[17];
    const float* bn_beta  = (const float*)d_in[18];
    float* out = (float*)d_out;

    float *xp, *qb, *kb, *sim, *msim, *biasb, *invq, *invk, *mbias;
    __half *vh, *xh, *msimh, *scwh;
    cudaGetSymbolAddress((void**)&xp,   g_xp);
    cudaGetSymbolAddress((void**)&qb,   g_q);
    cudaGetSymbolAddress((void**)&kb,   g_k);
    cudaGetSymbolAddress((void**)&vh,   g_vh);
    cudaGetSymbolAddress((void**)&xh,   g_xh);
    cudaGetSymbolAddress((void**)&sim,  g_sim);
    cudaGetSymbolAddress((void**)&msim, g_msim);
    cudaGetSymbolAddress((void**)&msimh,g_msimh);
    cudaGetSymbolAddress((void**)&scwh, g_scwh);
    cudaGetSymbolAddress((void**)&biasb,g_bias);
    cudaGetSymbolAddress((void**)&invq, g_invq);
    cudaGetSymbolAddress((void**)&invk, g_invk);
    cudaGetSymbolAddress((void**)&mbias,g_mbias);

    const int dw_smem    = 128 * 129 * 4;                          // 66048
    const int mma_smem   = 2 * (A_WORDS + B_WORDS) * 4;            // 71680
    const int sim_smem   = 4 * A_WORDS * 4;                        // 73728
    const int fus_smem   = 2 * (AH_HALF + BH_HALF) * 2;            // 37888
    cudaFuncSetAttribute(k_dw,      cudaFuncAttributeMaxDynamicSharedMemorySize, dw_smem);
    cudaFuncSetAttribute(k_projsim, cudaFuncAttributeMaxDynamicSharedMemorySize, mma_smem);
    cudaFuncSetAttribute(k_simmma,  cudaFuncAttributeMaxDynamicSharedMemorySize, sim_smem);
    cudaFuncSetAttribute(k_fused,   cudaFuncAttributeMaxDynamicSharedMemorySize, fus_smem);

    // 1. maxpool 4x4 (+ x -> half)
    k_maxpool<<<(NB*NC*LP)/256, 256>>>(x, xp, xh);
    // 2/3. q,k grouped pw on pooled
    k_grouped_pw<<<dim3(LP/128, NG, NB), 128>>>(xp, q_w, q_b, qb, LP);
    k_grouped_pw<<<dim3(LP/128, NG, NB), 128>>>(xp, k_w, k_b, kb, LP);
    // 4. depthwise 3x3 + relu on xh -> vdh  [profiled slot]
    k_dw<<<dim3(NC, NB), 256, dw_smem>>>(xh, v_dw_w, v_dw_b, vh);
    // 5. inverse row norms
    k_rownorm<<<2048, 256>>>(qb, kb, invq, invk);
    // 6. sc_w -> half
    k_whalf<<<256, 256>>>(sc_w, scwh);
    // 7. CPB bias table
    k_cpb<<<256, 256>>>(cpb_w1, cpb_b1, cpb_w2, biasb);
    // 8. sim GEMM (tf32 mma) + scale + bias
    k_simmma<<<dim3(2, 2, NB*NHH), 256, sim_smem>>>(qb, kb, invq, invk, logit_sc, biasb, sim);
    // 9. double softmax (warp per row)
    k_dsoftmax<<<1024, 256>>>(sim);
    // 10. msim = proj @ sim per (b,h)
    k_projsim<<<dim3(2, 2, NB*NHH), 256, mma_smem>>>(proj_w, sim, msim);
    // 11. fold pw conv into msim -> half + mbias
    k_fold<<<NB*NHH, 256>>>(msim, v_pw_w, v_pw_b, msimh, mbias);
    // 12. out = gelu(msimh@vdh + pb + mbias)*bn + relu(scwh@xh + scb)  (fp16 HMMA + ldmatrix)
    k_fused<<<dim3(HWSZ/128, 2, NB), 256, fus_smem>>>(msimh, vh, scwh, xh, out,
                                                      proj_b, bn_gamma, bn_beta, sc_b, mbias);
}